// round 2
// baseline (speedup 1.0000x reference)
#include <cuda_runtime.h>
#include <cstdint>

// ---------------------------------------------------------------------------
// Problem constants
// ---------------------------------------------------------------------------
#define BATCH   512
#define MAXLEN  128
#define D_DRUG  256
#define D_CELL  1024
#define NHEAD   16
#define HDIM    64
#define EMB     1024   // NHEAD*HDIM
#define KSPLIT  4      // K-slices for the big 1024-K GEMMs

// ---------------------------------------------------------------------------
// Scratch (device globals: allocation-free, sanctioned by harness rules)
// ---------------------------------------------------------------------------
__device__ float g_cq  [BATCH * EMB];            // cell query fc out
__device__ float g_q   [BATCH * EMB];            // scaled q
__device__ float g_qk  [BATCH * NHEAD * D_DRUG]; // q folded through Wk (per head)
__device__ float g_xa  [BATCH * NHEAD * D_DRUG]; // attn-weighted x sums
__device__ float g_op  [BATCH * EMB];            // pre-Wo output
__device__ float g_part[KSPLIT * BATCH * EMB];   // split-K partials (8 MB)
__device__ int   g_seg [BATCH + 1];              // segment starts

// ---------------------------------------------------------------------------
// Packed f32x2 FMA helpers (sm_103a: doubles FFMA throughput vs scalar)
// ---------------------------------------------------------------------------
union F2U { float2 f; unsigned long long u; };

__device__ __forceinline__ void fma2(F2U &c, F2U a, F2U b) {
    asm("fma.rn.f32x2 %0, %1, %2, %0;" : "+l"(c.u) : "l"(a.u), "l"(b.u));
}

// ---------------------------------------------------------------------------
// Segment starts: lower_bound binary search per graph id.
// Handles guide stored as int32 OR int64 (auto-detect from top bytes).
// ---------------------------------------------------------------------------
__global__ void seg_kernel(const void* __restrict__ guide, int n, int* __restrict__ seg)
{
    int g = blockIdx.x * blockDim.x + threadIdx.x;
    if (g > BATCH) return;
    const unsigned long long* g64 = (const unsigned long long*)guide;
    const int*                g32 = (const int*)guide;
    bool is64 = (g64[(n >> 1) - 1] <= 511ull);
    int lo = 0, hi = n;
    while (lo < hi) {
        int mid = (lo + hi) >> 1;
        long long v = is64 ? (long long)g64[mid] : (long long)g32[mid];
        if (v < (long long)g) lo = mid + 1; else hi = mid;
    }
    seg[g] = lo;
}

// ---------------------------------------------------------------------------
// Copy cell -> out[:, EMB : EMB+D_CELL]
// ---------------------------------------------------------------------------
__global__ void copy_cell_kernel(const float4* __restrict__ cell, float4* __restrict__ out)
{
    int i = blockIdx.x * blockDim.x + threadIdx.x;   // BATCH * (D_CELL/4) = 131072
    if (i >= BATCH * (D_CELL / 4)) return;
    int b = i >> 8, j = i & 255;                     // 256 float4 per row
    out[b * ((EMB + D_CELL) / 4) + (EMB / 4) + j] = cell[i];
}

// ---------------------------------------------------------------------------
// Split-K reduce: out[b, j] = alpha * (sum_s part[s][b, j] + bias[j])
// Works on [512, 1024] logical tiles; ldc4 = out row stride in float4.
// Fixed summation order -> deterministic.
// ---------------------------------------------------------------------------
__global__ __launch_bounds__(256)
void reduce_kernel(const float4* __restrict__ part, const float4* __restrict__ bias,
                   float4* __restrict__ outp, int ldc4, float alpha, int ns)
{
    int i = blockIdx.x * blockDim.x + threadIdx.x;   // 512*256
    if (i >= BATCH * (EMB / 4)) return;
    int b = i >> 8, j = i & 255;
    float4 s = part[i];
    for (int k = 1; k < ns; k++) {
        float4 p = part[(long long)k * BATCH * (EMB / 4) + i];
        s.x += p.x; s.y += p.y; s.z += p.z; s.w += p.w;
    }
    float4 bb = bias ? bias[j] : make_float4(0.f, 0.f, 0.f, 0.f);
    float4 o;
    o.x = alpha * (s.x + bb.x);
    o.y = alpha * (s.y + bb.y);
    o.z = alpha * (s.z + bb.z);
    o.w = alpha * (s.w + bb.w);
    outp[(long long)b * ldc4 + j] = o;
}

// ---------------------------------------------------------------------------
// SGEMM: C = alpha * (A x op(W) + bias_row)
//   TRANS_W = true : W is [N,K] row-major (both operands K-contiguous, "NT")
//   TRANS_W = false: W is [K,N] row-major ("NN")
// Tile 64x64x16, 256 threads, 4x4 microtile, f32x2 accumulation,
// double-buffered smem with register prefetch.
// blockIdx.z = batch slice (head or K-slice), with explicit z-strides.
// ---------------------------------------------------------------------------
#define BM 64
#define BN 64
#define BKK 16
#define SPAD 68

template <bool TRANS_W>
__global__ __launch_bounds__(256, 4)
void sgemm_kernel(int M, int N, int K,
                  const float* __restrict__ A, int lda, long long sAz,
                  const float* __restrict__ W, int ldw, long long sWz,
                  const float* __restrict__ bias, long long sbz,
                  float* __restrict__ C, int ldc, long long sCz,
                  float alpha)
{
    __shared__ float As[2][BKK * SPAD];
    __shared__ float Ws[2][BKK * SPAD];

    int z = blockIdx.z;
    A += (long long)z * sAz;
    W += (long long)z * sWz;
    C += (long long)z * sCz;
    const float* biasp = bias ? bias + (long long)z * sbz : nullptr;

    int m0 = blockIdx.y * BM;
    int n0 = blockIdx.x * BN;
    int tid = threadIdx.x;

    int arow = tid >> 2;
    int akq  = (tid & 3) * 4;
    int bkr  = tid >> 4;
    int bnq  = (tid & 15) * 4;

    const float* Aptr = A + (long long)(m0 + arow) * lda + akq;
    const float* Wptr = TRANS_W ? (W + (long long)(n0 + arow) * ldw + akq)
                                : (W + (long long)bkr * ldw + n0 + bnq);

    int tm = (tid >> 4) * 4;
    int tn = (tid & 15) * 4;

    F2U acc[4][2];
#pragma unroll
    for (int i = 0; i < 4; i++) { acc[i][0].f = make_float2(0.f, 0.f); acc[i][1].f = make_float2(0.f, 0.f); }

    float4 ra = *(const float4*)Aptr;
    float4 rw = *(const float4*)Wptr;
    {
        As[0][(akq + 0) * SPAD + arow] = ra.x;
        As[0][(akq + 1) * SPAD + arow] = ra.y;
        As[0][(akq + 2) * SPAD + arow] = ra.z;
        As[0][(akq + 3) * SPAD + arow] = ra.w;
        if (TRANS_W) {
            Ws[0][(akq + 0) * SPAD + arow] = rw.x;
            Ws[0][(akq + 1) * SPAD + arow] = rw.y;
            Ws[0][(akq + 2) * SPAD + arow] = rw.z;
            Ws[0][(akq + 3) * SPAD + arow] = rw.w;
        } else {
            *(float4*)&Ws[0][bkr * SPAD + bnq] = rw;
        }
    }
    __syncthreads();

    int KT = K / BKK;
    int buf = 0;
    for (int kt = 0; kt < KT; kt++) {
        if (kt + 1 < KT) {
            ra = *(const float4*)(Aptr + (long long)(kt + 1) * BKK);
            rw = TRANS_W ? *(const float4*)(Wptr + (long long)(kt + 1) * BKK)
                         : *(const float4*)(Wptr + (long long)(kt + 1) * BKK * ldw);
        }

        const float* pa = &As[buf][0];
        const float* pw = &Ws[buf][0];
#pragma unroll
        for (int kk = 0; kk < BKK; kk++) {
            float4 av = *(const float4*)(pa + kk * SPAD + tm);
            float4 bv = *(const float4*)(pw + kk * SPAD + tn);
            F2U b0, b1, a;
            b0.f = make_float2(bv.x, bv.y);
            b1.f = make_float2(bv.z, bv.w);
            a.f = make_float2(av.x, av.x); fma2(acc[0][0], a, b0); fma2(acc[0][1], a, b1);
            a.f = make_float2(av.y, av.y); fma2(acc[1][0], a, b0); fma2(acc[1][1], a, b1);
            a.f = make_float2(av.z, av.z); fma2(acc[2][0], a, b0); fma2(acc[2][1], a, b1);
            a.f = make_float2(av.w, av.w); fma2(acc[3][0], a, b0); fma2(acc[3][1], a, b1);
        }

        if (kt + 1 < KT) {
            int nb = buf ^ 1;
            As[nb][(akq + 0) * SPAD + arow] = ra.x;
            As[nb][(akq + 1) * SPAD + arow] = ra.y;
            As[nb][(akq + 2) * SPAD + arow] = ra.z;
            As[nb][(akq + 3) * SPAD + arow] = ra.w;
            if (TRANS_W) {
                Ws[nb][(akq + 0) * SPAD + arow] = rw.x;
                Ws[nb][(akq + 1) * SPAD + arow] = rw.y;
                Ws[nb][(akq + 2) * SPAD + arow] = rw.z;
                Ws[nb][(akq + 3) * SPAD + arow] = rw.w;
            } else {
                *(float4*)&Ws[nb][bkr * SPAD + bnq] = rw;
            }
        }
        __syncthreads();
        buf ^= 1;
    }

    float b4[4] = {0.f, 0.f, 0.f, 0.f};
    if (biasp) {
        b4[0] = biasp[n0 + tn + 0];
        b4[1] = biasp[n0 + tn + 1];
        b4[2] = biasp[n0 + tn + 2];
        b4[3] = biasp[n0 + tn + 3];
    }
#pragma unroll
    for (int i = 0; i < 4; i++) {
        float4 o;
        o.x = alpha * (acc[i][0].f.x + b4[0]);
        o.y = alpha * (acc[i][0].f.y + b4[1]);
        o.z = alpha * (acc[i][1].f.x + b4[2]);
        o.w = alpha * (acc[i][1].f.y + b4[3]);
        *(float4*)(C + (long long)(m0 + tm + i) * ldc + n0 + tn) = o;
    }
}

// ---------------------------------------------------------------------------
// Fused attention: per-graph scores -> softmax -> attn-weighted x sums.
// One block per graph, 256 threads.
// ---------------------------------------------------------------------------
__global__ __launch_bounds__(256)
void attn_kernel(const float* __restrict__ x,
                 const float* __restrict__ qk,
                 const int*   __restrict__ seg,
                 float*       __restrict__ xa)
{
    __shared__ float qks[16 * 260];
    __shared__ float xs [16 * 260];
    __shared__ float sc [16 * 132];

    int b = blockIdx.x;
    int t = threadIdx.x;
    int s0 = seg[b];
    int len = seg[b + 1] - s0;
    if (len > MAXLEN) len = MAXLEN;

    const float4* qk4 = (const float4*)(qk + (long long)b * (NHEAD * D_DRUG));
#pragma unroll
    for (int r = 0; r < 4; r++) {
        int idx = t + r * 256;
        int h = idx >> 6, jj = idx & 63;
        *(float4*)&qks[h * 260 + jj * 4] = qk4[idx];
    }
    __syncthreads();

    int hh = t >> 4, mm = t & 15;
    for (int m0 = 0; m0 < len; m0 += 16) {
        int nm = len - m0; if (nm > 16) nm = 16;
#pragma unroll
        for (int r = 0; r < 4; r++) {
            int idx = t + r * 256;
            int row = idx >> 6, jj = idx & 63;
            if (row < nm)
                *(float4*)&xs[row * 260 + jj * 4] =
                    *(const float4*)(x + (long long)(s0 + m0 + row) * D_DRUG + jj * 4);
        }
        __syncthreads();
        if (mm < nm) {
            const float* qp = &qks[hh * 260];
            const float* xp = &xs[mm * 260];
            F2U acc0, acc1;
            acc0.f = make_float2(0.f, 0.f);
            acc1.f = make_float2(0.f, 0.f);
#pragma unroll
            for (int j = 0; j < 256; j += 8) {
                float4 a0 = *(const float4*)(qp + j);
                float4 b0 = *(const float4*)(xp + j);
                float4 a1 = *(const float4*)(qp + j + 4);
                float4 b1 = *(const float4*)(xp + j + 4);
                F2U aa, bb;
                aa.f = make_float2(a0.x, a0.y); bb.f = make_float2(b0.x, b0.y); fma2(acc0, aa, bb);
                aa.f = make_float2(a0.z, a0.w); bb.f = make_float2(b0.z, b0.w); fma2(acc1, aa, bb);
                aa.f = make_float2(a1.x, a1.y); bb.f = make_float2(b1.x, b1.y); fma2(acc0, aa, bb);
                aa.f = make_float2(a1.z, a1.w); bb.f = make_float2(b1.z, b1.w); fma2(acc1, aa, bb);
            }
            sc[hh * 132 + m0 + mm] = acc0.f.x + acc0.f.y + acc1.f.x + acc1.f.y;
        }
        __syncthreads();
    }

    int w = t >> 5, lane = t & 31;
#pragma unroll
    for (int hq = 0; hq < 2; hq++) {
        int h = w * 2 + hq;
        float mx = -3.0e38f;
        for (int m = lane; m < len; m += 32) mx = fmaxf(mx, sc[h * 132 + m]);
#pragma unroll
        for (int o = 16; o; o >>= 1) mx = fmaxf(mx, __shfl_xor_sync(0xffffffffu, mx, o));
        float sum = 0.f;
        for (int m = lane; m < len; m += 32) {
            float e = __expf(sc[h * 132 + m] - mx);
            sc[h * 132 + m] = e;
            sum += e;
        }
#pragma unroll
        for (int o = 16; o; o >>= 1) sum += __shfl_xor_sync(0xffffffffu, sum, o);
        float inv = 1.0f / sum;
        for (int m = lane; m < len; m += 32) sc[h * 132 + m] *= inv;
    }
    __syncthreads();

    int h = t >> 4;
    int j0 = (t & 15) * 16;
    F2U acc[8];
#pragma unroll
    for (int i = 0; i < 8; i++) acc[i].f = make_float2(0.f, 0.f);
    for (int m = 0; m < len; m++) {
        float a = sc[h * 132 + m];
        F2U ad; ad.f = make_float2(a, a);
        const float4* xr = (const float4*)(x + (long long)(s0 + m) * D_DRUG + j0);
#pragma unroll
        for (int r = 0; r < 4; r++) {
            float4 v = xr[r];
            F2U b0, b1;
            b0.f = make_float2(v.x, v.y);
            b1.f = make_float2(v.z, v.w);
            fma2(acc[2 * r], ad, b0);
            fma2(acc[2 * r + 1], ad, b1);
        }
    }
    float* xo = xa + (long long)b * (NHEAD * D_DRUG) + h * D_DRUG + j0;
#pragma unroll
    for (int r = 0; r < 4; r++) {
        float4 o = make_float4(acc[2 * r].f.x, acc[2 * r].f.y,
                               acc[2 * r + 1].f.x, acc[2 * r + 1].f.y);
        *(float4*)(xo + r * 4) = o;
    }
}

// ---------------------------------------------------------------------------
// Launch
// ---------------------------------------------------------------------------
extern "C" void kernel_launch(void* const* d_in, const int* in_sizes, int n_in,
                              void* d_out, int out_size)
{
    const float* x_nodes = (const float*)d_in[0];
    const float* cell    = (const float*)d_in[1];
    const float* Wq      = (const float*)d_in[2];
    const float* bq      = (const float*)d_in[3];
    const float* Wk      = (const float*)d_in[4];
    /* bk = d_in[5]: cancels exactly in softmax */
    const float* Wv      = (const float*)d_in[6];
    const float* bv      = (const float*)d_in[7];
    const float* Wo      = (const float*)d_in[8];
    const float* bo      = (const float*)d_in[9];
    const float* Wc      = (const float*)d_in[10];
    const float* bc      = (const float*)d_in[11];
    const void*  guide   = d_in[12];
    float*       out     = (float*)d_out;

    int N = in_sizes[12];

    float *cq, *q, *qkp, *xap, *op, *part;
    int* seg;
    cudaGetSymbolAddress((void**)&cq,   g_cq);
    cudaGetSymbolAddress((void**)&q,    g_q);
    cudaGetSymbolAddress((void**)&qkp,  g_qk);
    cudaGetSymbolAddress((void**)&xap,  g_xa);
    cudaGetSymbolAddress((void**)&op,   g_op);
    cudaGetSymbolAddress((void**)&part, g_part);
    cudaGetSymbolAddress((void**)&seg,  g_seg);

    const long long PART_Z = (long long)BATCH * EMB;   // per-slice partial stride
    const int KS = EMB / KSPLIT;                       // 256 per K-slice

    // independent prep
    seg_kernel<<<3, 256>>>(guide, N, seg);
    copy_cell_kernel<<<512, 256>>>((const float4*)cell, (float4*)out);

    // cq = cell @ Wc^T + bc   (split-K=4: one full wave at occ 50%)
    sgemm_kernel<true><<<dim3(16, 8, KSPLIT), 256>>>(512, 1024, KS,
        cell, 1024, KS, Wc, 1024, KS, nullptr, 0, part, 1024, PART_Z, 1.0f);
    reduce_kernel<<<512, 256>>>((const float4*)part, (const float4*)bc,
                                (float4*)cq, EMB / 4, 1.0f, KSPLIT);

    // q = (cq @ Wq^T + bq) * HD^-0.5
    sgemm_kernel<true><<<dim3(16, 8, KSPLIT), 256>>>(512, 1024, KS,
        cq, 1024, KS, Wq, 1024, KS, nullptr, 0, part, 1024, PART_Z, 1.0f);
    reduce_kernel<<<512, 256>>>((const float4*)part, (const float4*)bq,
                                (float4*)q, EMB / 4, 0.125f, KSPLIT);

    // qk[b,h,:] = q[b,h,:] @ Wk_h     16 x ([512,64]x[64,256], NN), grid 512
    sgemm_kernel<false><<<dim3(4, 8, 16), 256>>>(512, 256, 64,
        q, 1024, 64, Wk, 256, 64 * 256, nullptr, 0, qkp, 4096, 256, 1.0f);

    // fused scores -> softmax -> xa
    attn_kernel<<<512, 256>>>(x_nodes, qkp, seg, xap);

    // out_pre[b,h,:] = xa[b,h,:] @ Wv_h^T + bv_h  16 x ([512,256]x[256,64], NT)
    sgemm_kernel<true><<<dim3(1, 8, 16), 256>>>(512, 64, 256,
        xap, 4096, 256, Wv, 256, 64 * 256, bv, 64, op, 1024, 64, 1.0f);

    // out[:, :1024] = out_pre @ Wo^T + bo   (split-K=4)
    sgemm_kernel<true><<<dim3(16, 8, KSPLIT), 256>>>(512, 1024, KS,
        op, 1024, KS, Wo, 1024, KS, nullptr, 0, part, 1024, PART_Z, 1.0f);
    reduce_kernel<<<512, 256>>>((const float4*)part, (const float4*)bo,
                                (float4*)out, (EMB + D_CELL) / 4, 1.0f, KSPLIT);

    (void)n_in; (void)out_size;
}

// round 4
// speedup vs baseline: 1.2522x; 1.2522x over previous
#include <cuda_runtime.h>
#include <cuda_bf16.h>
#include <cstdint>

// ---------------------------------------------------------------------------
// Problem constants
// ---------------------------------------------------------------------------
#define BATCH   512
#define MAXLEN  128
#define D_DRUG  256
#define D_CELL  1024
#define NHEAD   16
#define HDIM    64
#define EMB     1024   // NHEAD*HDIM

// ---------------------------------------------------------------------------
// Scratch (device globals: allocation-free, sanctioned by harness rules)
// ---------------------------------------------------------------------------
__device__ float g_qk [BATCH * NHEAD * D_DRUG];  // q folded through Wk (fp32)
__device__ int   g_seg[BATCH + 1];

// bf16 hi/lo pairs
__device__ __nv_bfloat16 g_a0h[BATCH * EMB],   g_a0l[BATCH * EMB];    // cell, then q
__device__ __nv_bfloat16 g_a1h[BATCH * EMB],   g_a1l[BATCH * EMB];    // cq, then op
__device__ __nv_bfloat16 g_xah[BATCH * NHEAD * D_DRUG], g_xal[BATCH * NHEAD * D_DRUG];
__device__ __nv_bfloat16 g_wch[EMB * D_CELL],  g_wcl[EMB * D_CELL];
__device__ __nv_bfloat16 g_wqh[EMB * EMB],     g_wql[EMB * EMB];
__device__ __nv_bfloat16 g_woh[EMB * EMB],     g_wol[EMB * EMB];
__device__ __nv_bfloat16 g_wvh[EMB * D_DRUG],  g_wvl[EMB * D_DRUG];
__device__ __nv_bfloat16 g_wkth[NHEAD * D_DRUG * HDIM], g_wktl[NHEAD * D_DRUG * HDIM];

// ---------------------------------------------------------------------------
// Helpers
// ---------------------------------------------------------------------------
union F2U { float2 f; unsigned long long u; };
__device__ __forceinline__ void fma2(F2U &c, F2U a, F2U b) {
    asm("fma.rn.f32x2 %0, %1, %2, %0;" : "+l"(c.u) : "l"(a.u), "l"(b.u));
}

__device__ __forceinline__ uint32_t smem_u32(const void* p) {
    uint32_t a;
    asm("{ .reg .u64 t; cvta.to.shared.u64 t, %1; cvt.u32.u64 %0, t; }" : "=r"(a) : "l"(p));
    return a;
}

__device__ __forceinline__ void ldsm4(uint32_t &r0, uint32_t &r1, uint32_t &r2, uint32_t &r3,
                                      uint32_t a) {
    asm volatile("ldmatrix.sync.aligned.m8n8.x4.shared.b16 {%0,%1,%2,%3}, [%4];"
        : "=r"(r0), "=r"(r1), "=r"(r2), "=r"(r3) : "r"(a));
}

__device__ __forceinline__ void mma_bf16(float c[4], const uint32_t a[4],
                                         uint32_t b0, uint32_t b1) {
    asm volatile("mma.sync.aligned.m16n8k16.row.col.f32.bf16.bf16.f32 "
        "{%0,%1,%2,%3}, {%4,%5,%6,%7}, {%8,%9}, {%0,%1,%2,%3};"
        : "+f"(c[0]), "+f"(c[1]), "+f"(c[2]), "+f"(c[3])
        : "r"(a[0]), "r"(a[1]), "r"(a[2]), "r"(a[3]), "r"(b0), "r"(b1));
}

__device__ __forceinline__ uint32_t pack_bf16(float a, float b) {
    return (uint32_t)__bfloat16_as_ushort(__float2bfloat16(a))
         | ((uint32_t)__bfloat16_as_ushort(__float2bfloat16(b)) << 16);
}

// ---------------------------------------------------------------------------
// Segment starts (int32/int64 guide auto-detect)
// ---------------------------------------------------------------------------
__global__ void seg_kernel(const void* __restrict__ guide, int n, int* __restrict__ seg)
{
    int g = blockIdx.x * blockDim.x + threadIdx.x;
    if (g > BATCH) return;
    const unsigned long long* g64 = (const unsigned long long*)guide;
    const int*                g32 = (const int*)guide;
    bool is64 = (g64[(n >> 1) - 1] <= 511ull);
    int lo = 0, hi = n;
    while (lo < hi) {
        int mid = (lo + hi) >> 1;
        long long v = is64 ? (long long)g64[mid] : (long long)g32[mid];
        if (v < (long long)g) lo = mid + 1; else hi = mid;
    }
    seg[g] = lo;
}

// ---------------------------------------------------------------------------
// Copy cell -> out[:, EMB:EMB+D_CELL]
// ---------------------------------------------------------------------------
__global__ void copy_cell_kernel(const float4* __restrict__ cell, float4* __restrict__ out)
{
    int i = blockIdx.x * blockDim.x + threadIdx.x;
    if (i >= BATCH * (D_CELL / 4)) return;
    int b = i >> 8, j = i & 255;
    out[b * ((EMB + D_CELL) / 4) + (EMB / 4) + j] = cell[i];
}

// ---------------------------------------------------------------------------
// fp32 -> (bf16 hi, bf16 lo) split
// ---------------------------------------------------------------------------
__global__ __launch_bounds__(256)
void split_kernel(const float4* __restrict__ s, uint2* __restrict__ hi,
                  uint2* __restrict__ lo, int n4)
{
    int i = blockIdx.x * 256 + threadIdx.x;
    if (i >= n4) return;
    float4 v = s[i];
    __nv_bfloat16 h0 = __float2bfloat16(v.x), h1 = __float2bfloat16(v.y);
    __nv_bfloat16 h2 = __float2bfloat16(v.z), h3 = __float2bfloat16(v.w);
    uint2 H, L;
    H.x = (uint32_t)__bfloat16_as_ushort(h0) | ((uint32_t)__bfloat16_as_ushort(h1) << 16);
    H.y = (uint32_t)__bfloat16_as_ushort(h2) | ((uint32_t)__bfloat16_as_ushort(h3) << 16);
    L.x = pack_bf16(v.x - __bfloat162float(h0), v.y - __bfloat162float(h1));
    L.y = pack_bf16(v.z - __bfloat162float(h2), v.w - __bfloat162float(h3));
    hi[i] = H; lo[i] = L;
}

// ---------------------------------------------------------------------------
// Wk transpose-split: out[h][n][d] = Wk[h*64+d][n], as bf16 hi/lo.
// grid (8, 2, 16), block 256 (32x8, each thread 4 rows)
// ---------------------------------------------------------------------------
__global__ __launch_bounds__(256)
void splitT_wk(const float* __restrict__ Wk,
               __nv_bfloat16* __restrict__ oh, __nv_bfloat16* __restrict__ ol)
{
    __shared__ float tile[32][33];
    int h = blockIdx.z, nt = blockIdx.x, dt = blockIdx.y;
    int tx = threadIdx.x & 31, ty = threadIdx.x >> 5;
#pragma unroll
    for (int r = ty; r < 32; r += 8)
        tile[r][tx] = Wk[(long long)(h * 64 + dt * 32 + r) * D_DRUG + nt * 32 + tx];
    __syncthreads();
#pragma unroll
    for (int r = ty; r < 32; r += 8) {
        float v = tile[tx][r];
        __nv_bfloat16 hh = __float2bfloat16(v);
        long long o = (long long)h * (D_DRUG * HDIM) + (long long)(nt * 32 + r) * HDIM + dt * 32 + tx;
        oh[o] = hh;
        ol[o] = __float2bfloat16(v - __bfloat162float(hh));
    }
}

// ---------------------------------------------------------------------------
// bf16x3 MMA GEMM:  C[M, N] = alpha * (A[M,K] * W[N,K]^T + bias)
// A, W as bf16 (hi, lo) pairs, K-contiguous rows, element strides lda/ldw,
// batched via blockIdx.z with element strides sAz/sWz/sbz/sCz.
// CTA tile 64x64, 128 threads (4 warps, 2x2 grid of 32x32 warp tiles).
// 3 products in fp32 accum: Ah*Wh + Ah*Wl + Al*Wh.
// MODE 0: write bf16 hi/lo split of alpha*(acc+bias) to Ch/Cl
// MODE 1: write fp32 to Cf
// Requires M%64==0, N%64==0, K%32==0.
// ---------------------------------------------------------------------------
template <int MODE>
__global__ __launch_bounds__(128)
void mma_gemm3x(const __nv_bfloat16* __restrict__ Ah, const __nv_bfloat16* __restrict__ Al,
                int lda, long long sAz,
                const __nv_bfloat16* __restrict__ Wh, const __nv_bfloat16* __restrict__ Wl,
                int ldw, long long sWz,
                const float* __restrict__ bias, long long sbz,
                float* __restrict__ Cf,
                __nv_bfloat16* __restrict__ Ch, __nv_bfloat16* __restrict__ Cl,
                int ldc, long long sCz, float alpha, int K)
{
    // smem: buf stride 20480; arrays: Ah@0, Al@5120, Bh@10240, Bl@15360 (64 rows x 80B)
    __shared__ __align__(16) char smraw[40960];

    int z = blockIdx.z;
    const __nv_bfloat16* Ah_ = Ah + (long long)z * sAz;
    const __nv_bfloat16* Al_ = Al + (long long)z * sAz;
    const __nv_bfloat16* Wh_ = Wh + (long long)z * sWz;
    const __nv_bfloat16* Wl_ = Wl + (long long)z * sWz;
    const float* bp = bias ? bias + (long long)z * sbz : nullptr;
    long long coff = (long long)z * sCz;

    int tid = threadIdx.x, lane = tid & 31, warp = tid >> 5;
    int wm = warp >> 1, wn = warp & 1;
    int m0 = blockIdx.y * 64, n0 = blockIdx.x * 64;

    // loader mapping: thread -> (row = tid/4 and +32, 16B quad = tid%4)
    int lr0 = tid >> 2, lr1 = lr0 + 32;
    int lq  = (tid & 3) * 8;                 // element col
    int lo0 = lr0 * 80 + (tid & 3) * 16;     // smem byte offset
    int lo1 = lr1 * 80 + (tid & 3) * 16;

    const __nv_bfloat16* pAh0 = Ah_ + (long long)(m0 + lr0) * lda + lq;
    const __nv_bfloat16* pAh1 = Ah_ + (long long)(m0 + lr1) * lda + lq;
    const __nv_bfloat16* pAl0 = Al_ + (long long)(m0 + lr0) * lda + lq;
    const __nv_bfloat16* pAl1 = Al_ + (long long)(m0 + lr1) * lda + lq;
    const __nv_bfloat16* pWh0 = Wh_ + (long long)(n0 + lr0) * ldw + lq;
    const __nv_bfloat16* pWh1 = Wh_ + (long long)(n0 + lr1) * ldw + lq;
    const __nv_bfloat16* pWl0 = Wl_ + (long long)(n0 + lr0) * ldw + lq;
    const __nv_bfloat16* pWl1 = Wl_ + (long long)(n0 + lr1) * ldw + lq;

    float acc[2][4][4];
#pragma unroll
    for (int s = 0; s < 2; s++)
#pragma unroll
        for (int nb = 0; nb < 4; nb++)
#pragma unroll
            for (int i = 0; i < 4; i++) acc[s][nb][i] = 0.f;

    // prologue: tile 0 -> buf 0
    {
        char* s = smraw;
        *(uint4*)(s + lo0)          = *(const uint4*)pAh0;
        *(uint4*)(s + lo1)          = *(const uint4*)pAh1;
        *(uint4*)(s + 5120  + lo0)  = *(const uint4*)pAl0;
        *(uint4*)(s + 5120  + lo1)  = *(const uint4*)pAl1;
        *(uint4*)(s + 10240 + lo0)  = *(const uint4*)pWh0;
        *(uint4*)(s + 10240 + lo1)  = *(const uint4*)pWh1;
        *(uint4*)(s + 15360 + lo0)  = *(const uint4*)pWl0;
        *(uint4*)(s + 15360 + lo1)  = *(const uint4*)pWl1;
    }
    __syncthreads();

    uint32_t smb = smem_u32(smraw);
    // A frag addr: row = wm*32 + s*16 + (lane&15); k-half = (lane>>4)&1
    uint32_t aBase = smb + (uint32_t)((wm * 32 + (lane & 15)) * 80 + ((lane >> 4) & 1) * 16);
    // B frag addr: row = wn*32 + p*16 + ((lane>>4)&1)*8 + (lane&7); k-half = (lane>>3)&1
    uint32_t bBase = smb + 10240u +
        (uint32_t)((wn * 32 + ((lane >> 4) & 1) * 8 + (lane & 7)) * 80 + ((lane >> 3) & 1) * 16);

    int NT = K / 32;
    uint4 f0, f1, f2, f3, f4, f5, f6, f7;
    for (int t = 0; t < NT; t++) {
        uint32_t bufo = (uint32_t)(t & 1) * 20480u;
        if (t + 1 < NT) {
            int k0 = (t + 1) * 32;
            f0 = *(const uint4*)(pAh0 + k0);
            f1 = *(const uint4*)(pAh1 + k0);
            f2 = *(const uint4*)(pAl0 + k0);
            f3 = *(const uint4*)(pAl1 + k0);
            f4 = *(const uint4*)(pWh0 + k0);
            f5 = *(const uint4*)(pWh1 + k0);
            f6 = *(const uint4*)(pWl0 + k0);
            f7 = *(const uint4*)(pWl1 + k0);
        }
#pragma unroll
        for (int kk = 0; kk < 2; kk++) {
            uint32_t ah[2][4], alr[2][4];
#pragma unroll
            for (int s = 0; s < 2; s++) {
                uint32_t ad = aBase + bufo + (uint32_t)(s * 1280 + kk * 32);
                ldsm4(ah[s][0], ah[s][1], ah[s][2], ah[s][3], ad);
                ldsm4(alr[s][0], alr[s][1], alr[s][2], alr[s][3], ad + 5120u);
            }
            uint32_t bh[4][2], blr[4][2];
#pragma unroll
            for (int p = 0; p < 2; p++) {
                uint32_t bd = bBase + bufo + (uint32_t)(p * 1280 + kk * 32);
                ldsm4(bh[2*p][0], bh[2*p][1], bh[2*p+1][0], bh[2*p+1][1], bd);
                ldsm4(blr[2*p][0], blr[2*p][1], blr[2*p+1][0], blr[2*p+1][1], bd + 5120u);
            }
#pragma unroll
            for (int s = 0; s < 2; s++)
#pragma unroll
                for (int nb = 0; nb < 4; nb++) {
                    mma_bf16(acc[s][nb], ah[s],  bh[nb][0],  bh[nb][1]);
                    mma_bf16(acc[s][nb], ah[s],  blr[nb][0], blr[nb][1]);
                    mma_bf16(acc[s][nb], alr[s], bh[nb][0],  bh[nb][1]);
                }
        }
        if (t + 1 < NT) {
            char* s = smraw + (bufo ^ 20480u);
            *(uint4*)(s + lo0)          = f0;
            *(uint4*)(s + lo1)          = f1;
            *(uint4*)(s + 5120  + lo0)  = f2;
            *(uint4*)(s + 5120  + lo1)  = f3;
            *(uint4*)(s + 10240 + lo0)  = f4;
            *(uint4*)(s + 10240 + lo1)  = f5;
            *(uint4*)(s + 15360 + lo0)  = f6;
            *(uint4*)(s + 15360 + lo1)  = f7;
            __syncthreads();
        }
    }

    // epilogue: C frag rows = lane/4 (+8), cols = 2*(lane%4) (+1)
    int erow = lane >> 2;
    int ecol = (lane & 3) * 2;
#pragma unroll
    for (int s = 0; s < 2; s++) {
        int r0 = m0 + wm * 32 + s * 16 + erow;
#pragma unroll
        for (int nb = 0; nb < 4; nb++) {
            int col = n0 + wn * 32 + nb * 8 + ecol;
            float b0 = bp ? bp[col] : 0.f;
            float b1 = bp ? bp[col + 1] : 0.f;
            float v00 = alpha * (acc[s][nb][0] + b0);
            float v01 = alpha * (acc[s][nb][1] + b1);
            float v10 = alpha * (acc[s][nb][2] + b0);
            float v11 = alpha * (acc[s][nb][3] + b1);
            if (MODE == 1) {
                *(float2*)(Cf + coff + (long long)r0 * ldc + col)       = make_float2(v00, v01);
                *(float2*)(Cf + coff + (long long)(r0 + 8) * ldc + col) = make_float2(v10, v11);
            } else {
                __nv_bfloat16 h00 = __float2bfloat16(v00), h01 = __float2bfloat16(v01);
                __nv_bfloat16 h10 = __float2bfloat16(v10), h11 = __float2bfloat16(v11);
                uint32_t ph0 = (uint32_t)__bfloat16_as_ushort(h00)
                             | ((uint32_t)__bfloat16_as_ushort(h01) << 16);
                uint32_t ph1 = (uint32_t)__bfloat16_as_ushort(h10)
                             | ((uint32_t)__bfloat16_as_ushort(h11) << 16);
                uint32_t pl0 = pack_bf16(v00 - __bfloat162float(h00), v01 - __bfloat162float(h01));
                uint32_t pl1 = pack_bf16(v10 - __bfloat162float(h10), v11 - __bfloat162float(h11));
                *(uint32_t*)(Ch + coff + (long long)r0 * ldc + col)       = ph0;
                *(uint32_t*)(Ch + coff + (long long)(r0 + 8) * ldc + col) = ph1;
                *(uint32_t*)(Cl + coff + (long long)r0 * ldc + col)       = pl0;
                *(uint32_t*)(Cl + coff + (long long)(r0 + 8) * ldc + col) = pl1;
            }
        }
    }
}

// ---------------------------------------------------------------------------
// Fused attention: scores -> softmax -> attn-weighted x sums (hi/lo bf16 out)
// One block per graph, 256 threads.
// ---------------------------------------------------------------------------
__global__ __launch_bounds__(256)
void attn_kernel(const float* __restrict__ x,
                 const float* __restrict__ qk,
                 const int*   __restrict__ seg,
                 __nv_bfloat16* __restrict__ xah,
                 __nv_bfloat16* __restrict__ xal)
{
    __shared__ float qks[16 * 260];
    __shared__ float xs [16 * 260];
    __shared__ float sc [16 * 132];

    int b = blockIdx.x;
    int t = threadIdx.x;
    int s0 = seg[b];
    int len = seg[b + 1] - s0;
    if (len > MAXLEN) len = MAXLEN;

    const float4* qk4 = (const float4*)(qk + (long long)b * (NHEAD * D_DRUG));
#pragma unroll
    for (int r = 0; r < 4; r++) {
        int idx = t + r * 256;
        int h = idx >> 6, jj = idx & 63;
        *(float4*)&qks[h * 260 + jj * 4] = qk4[idx];
    }
    __syncthreads();

    int hh = t >> 4, mm = t & 15;
    for (int m0 = 0; m0 < len; m0 += 16) {
        int nm = len - m0; if (nm > 16) nm = 16;
#pragma unroll
        for (int r = 0; r < 4; r++) {
            int idx = t + r * 256;
            int row = idx >> 6, jj = idx & 63;
            if (row < nm)
                *(float4*)&xs[row * 260 + jj * 4] =
                    *(const float4*)(x + (long long)(s0 + m0 + row) * D_DRUG + jj * 4);
        }
        __syncthreads();
        if (mm < nm) {
            const float* qp = &qks[hh * 260];
            const float* xp = &xs[mm * 260];
            F2U acc0, acc1;
            acc0.f = make_float2(0.f, 0.f);
            acc1.f = make_float2(0.f, 0.f);
#pragma unroll
            for (int j = 0; j < 256; j += 8) {
                float4 a0 = *(const float4*)(qp + j);
                float4 b0 = *(const float4*)(xp + j);
                float4 a1 = *(const float4*)(qp + j + 4);
                float4 b1 = *(const float4*)(xp + j + 4);
                F2U aa, bb;
                aa.f = make_float2(a0.x, a0.y); bb.f = make_float2(b0.x, b0.y); fma2(acc0, aa, bb);
                aa.f = make_float2(a0.z, a0.w); bb.f = make_float2(b0.z, b0.w); fma2(acc1, aa, bb);
                aa.f = make_float2(a1.x, a1.y); bb.f = make_float2(b1.x, b1.y); fma2(acc0, aa, bb);
                aa.f = make_float2(a1.z, a1.w); bb.f = make_float2(b1.z, b1.w); fma2(acc1, aa, bb);
            }
            sc[hh * 132 + m0 + mm] = acc0.f.x + acc0.f.y + acc1.f.x + acc1.f.y;
        }
        __syncthreads();
    }

    int w = t >> 5, lane = t & 31;
#pragma unroll
    for (int hq = 0; hq < 2; hq++) {
        int h = w * 2 + hq;
        float mx = -3.0e38f;
        for (int m = lane; m < len; m += 32) mx = fmaxf(mx, sc[h * 132 + m]);
#pragma unroll
        for (int o = 16; o; o >>= 1) mx = fmaxf(mx, __shfl_xor_sync(0xffffffffu, mx, o));
        float sum = 0.f;
        for (int m = lane; m < len; m += 32) {
            float e = __expf(sc[h * 132 + m] - mx);
            sc[h * 132 + m] = e;
            sum += e;
        }
#pragma unroll
        for (int o = 16; o; o >>= 1) sum += __shfl_xor_sync(0xffffffffu, sum, o);
        float inv = 1.0f / sum;
        for (int m = lane; m < len; m += 32) sc[h * 132 + m] *= inv;
    }
    __syncthreads();

    int h = t >> 4;
    int j0 = (t & 15) * 16;
    F2U acc[8];
#pragma unroll
    for (int i = 0; i < 8; i++) acc[i].f = make_float2(0.f, 0.f);
    for (int m = 0; m < len; m++) {
        float a = sc[h * 132 + m];
        F2U ad; ad.f = make_float2(a, a);
        const float4* xr = (const float4*)(x + (long long)(s0 + m) * D_DRUG + j0);
#pragma unroll
        for (int r = 0; r < 4; r++) {
            float4 v = xr[r];
            F2U b0, b1;
            b0.f = make_float2(v.x, v.y);
            b1.f = make_float2(v.z, v.w);
            fma2(acc[2 * r], ad, b0);
            fma2(acc[2 * r + 1], ad, b1);
        }
    }
    long long base = (long long)b * (NHEAD * D_DRUG) + h * D_DRUG + j0;
#pragma unroll
    for (int i = 0; i < 8; i++) {
        float va = acc[i].f.x, vb = acc[i].f.y;
        __nv_bfloat16 ha = __float2bfloat16(va), hb = __float2bfloat16(vb);
        uint32_t ph = (uint32_t)__bfloat16_as_ushort(ha)
                    | ((uint32_t)__bfloat16_as_ushort(hb) << 16);
        uint32_t pl = pack_bf16(va - __bfloat162float(ha), vb - __bfloat162float(hb));
        *(uint32_t*)(xah + base + i * 2) = ph;
        *(uint32_t*)(xal + base + i * 2) = pl;
    }
}

// ---------------------------------------------------------------------------
// Launch
// ---------------------------------------------------------------------------
extern "C" void kernel_launch(void* const* d_in, const int* in_sizes, int n_in,
                              void* d_out, int out_size)
{
    const float* x_nodes = (const float*)d_in[0];
    const float* cell    = (const float*)d_in[1];
    const float* Wq      = (const float*)d_in[2];
    const float* bq      = (const float*)d_in[3];
    const float* Wk      = (const float*)d_in[4];
    /* bk cancels in softmax */
    const float* Wv      = (const float*)d_in[6];
    const float* bv      = (const float*)d_in[7];
    const float* Wo      = (const float*)d_in[8];
    const float* bo      = (const float*)d_in[9];
    const float* Wc      = (const float*)d_in[10];
    const float* bc      = (const float*)d_in[11];
    const void*  guide   = d_in[12];
    float*       out     = (float*)d_out;

    int N = in_sizes[12];

    float* qkp; int* seg;
    __nv_bfloat16 *a0h, *a0l, *a1h, *a1l, *xah, *xal;
    __nv_bfloat16 *wch, *wcl, *wqh, *wql, *woh, *wol, *wvh, *wvl, *wkth, *wktl;
    cudaGetSymbolAddress((void**)&qkp,  g_qk);
    cudaGetSymbolAddress((void**)&seg,  g_seg);
    cudaGetSymbolAddress((void**)&a0h,  g_a0h);
    cudaGetSymbolAddress((void**)&a0l,  g_a0l);
    cudaGetSymbolAddress((void**)&a1h,  g_a1h);
    cudaGetSymbolAddress((void**)&a1l,  g_a1l);
    cudaGetSymbolAddress((void**)&xah,  g_xah);
    cudaGetSymbolAddress((void**)&xal,  g_xal);
    cudaGetSymbolAddress((void**)&wch,  g_wch);
    cudaGetSymbolAddress((void**)&wcl,  g_wcl);
    cudaGetSymbolAddress((void**)&wqh,  g_wqh);
    cudaGetSymbolAddress((void**)&wql,  g_wql);
    cudaGetSymbolAddress((void**)&woh,  g_woh);
    cudaGetSymbolAddress((void**)&wol,  g_wol);
    cudaGetSymbolAddress((void**)&wvh,  g_wvh);
    cudaGetSymbolAddress((void**)&wvl,  g_wvl);
    cudaGetSymbolAddress((void**)&wkth, g_wkth);
    cudaGetSymbolAddress((void**)&wktl, g_wktl);

    // prep
    seg_kernel<<<3, 256>>>(guide, N, seg);
    copy_cell_kernel<<<512, 256>>>((const float4*)cell, (float4*)out);
    split_kernel<<<512,  256>>>((const float4*)cell, (uint2*)a0h, (uint2*)a0l, BATCH * EMB / 4);
    split_kernel<<<1024, 256>>>((const float4*)Wc,   (uint2*)wch, (uint2*)wcl, EMB * D_CELL / 4);
    split_kernel<<<1024, 256>>>((const float4*)Wq,   (uint2*)wqh, (uint2*)wql, EMB * EMB / 4);
    split_kernel<<<1024, 256>>>((const float4*)Wo,   (uint2*)woh, (uint2*)wol, EMB * EMB / 4);
    split_kernel<<<256,  256>>>((const float4*)Wv,   (uint2*)wvh, (uint2*)wvl, EMB * D_DRUG / 4);
    splitT_wk<<<dim3(8, 2, 16), 256>>>(Wk, wkth, wktl);

    // G1: cq = cell @ Wc^T + bc     -> hi/lo (a1)
    mma_gemm3x<0><<<dim3(16, 8, 1), 128>>>(
        a0h, a0l, D_CELL, 0, wch, wcl, D_CELL, 0, bc, 0,
        nullptr, a1h, a1l, EMB, 0, 1.0f, D_CELL);

    // G2: q = (cq @ Wq^T + bq) * 0.125  -> hi/lo (a0, overwrites cell split)
    mma_gemm3x<0><<<dim3(16, 8, 1), 128>>>(
        a1h, a1l, EMB, 0, wqh, wql, EMB, 0, bq, 0,
        nullptr, a0h, a0l, EMB, 0, 0.125f, EMB);

    // qk[b,h,:] = q[b,h,:] @ WkT_h   16 x ([512,64] x [256,64]^T)  -> fp32
    mma_gemm3x<1><<<dim3(4, 8, 16), 128>>>(
        a0h, a0l, EMB, HDIM, wkth, wktl, HDIM, (long long)D_DRUG * HDIM, nullptr, 0,
        qkp, nullptr, nullptr, NHEAD * D_DRUG, D_DRUG, 1.0f, HDIM);

    // fused scores -> softmax -> xa (hi/lo)
    attn_kernel<<<512, 256>>>(x_nodes, qkp, seg, xah, xal);

    // vv: op[b, h*64+:] = xa[b,h,:] @ Wv_h^T + bv_h  -> hi/lo (a1)
    mma_gemm3x<0><<<dim3(1, 8, 16), 128>>>(
        xah, xal, NHEAD * D_DRUG, D_DRUG, wvh, wvl, D_DRUG, (long long)HDIM * D_DRUG, bv, HDIM,
        nullptr, a1h, a1l, EMB, HDIM, 1.0f, D_DRUG);

    // G3: out[:, :1024] = op @ Wo^T + bo  -> fp32 strided
    mma_gemm3x<1><<<dim3(16, 8, 1), 128>>>(
        a1h, a1l, EMB, 0, woh, wol, EMB, 0, bo, 0,
        out, nullptr, nullptr, EMB + D_CELL, 0, 1.0f, EMB);

    (void)n_in; (void)out_size;
}

// round 5
// speedup vs baseline: 1.2968x; 1.0356x over previous
#include <cuda_runtime.h>
#include <cuda_bf16.h>
#include <cstdint>

// ---------------------------------------------------------------------------
// Problem constants
// ---------------------------------------------------------------------------
#define BATCH   512
#define MAXLEN  128
#define D_DRUG  256
#define D_CELL  1024
#define NHEAD   16
#define HDIM    64
#define EMB     1024   // NHEAD*HDIM

// ---------------------------------------------------------------------------
// Scratch (device globals)
// ---------------------------------------------------------------------------
__device__ float g_qk  [BATCH * NHEAD * D_DRUG];   // q folded through Wk (fp32)
__device__ float g_part[4 * BATCH * EMB];          // split-K partials (8 MB)
__device__ int   g_seg [BATCH + 1];

__device__ __nv_bfloat16 g_a0h[BATCH * EMB],   g_a0l[BATCH * EMB];    // cell, then q
__device__ __nv_bfloat16 g_a1h[BATCH * EMB],   g_a1l[BATCH * EMB];    // cq, then op
__device__ __nv_bfloat16 g_xah[BATCH * NHEAD * D_DRUG], g_xal[BATCH * NHEAD * D_DRUG];
__device__ __nv_bfloat16 g_wch[EMB * D_CELL],  g_wcl[EMB * D_CELL];
__device__ __nv_bfloat16 g_wqh[EMB * EMB],     g_wql[EMB * EMB];
__device__ __nv_bfloat16 g_woh[EMB * EMB],     g_wol[EMB * EMB];
__device__ __nv_bfloat16 g_wvh[EMB * D_DRUG],  g_wvl[EMB * D_DRUG];
__device__ __nv_bfloat16 g_wkth[NHEAD * D_DRUG * HDIM], g_wktl[NHEAD * D_DRUG * HDIM];

// ---------------------------------------------------------------------------
// Helpers
// ---------------------------------------------------------------------------
union F2U { float2 f; unsigned long long u; };
__device__ __forceinline__ void fma2(F2U &c, F2U a, F2U b) {
    asm("fma.rn.f32x2 %0, %1, %2, %0;" : "+l"(c.u) : "l"(a.u), "l"(b.u));
}

__device__ __forceinline__ uint32_t smem_u32(const void* p) {
    uint32_t a;
    asm("{ .reg .u64 t; cvta.to.shared.u64 t, %1; cvt.u32.u64 %0, t; }" : "=r"(a) : "l"(p));
    return a;
}

__device__ __forceinline__ void ldsm4(uint32_t &r0, uint32_t &r1, uint32_t &r2, uint32_t &r3,
                                      uint32_t a) {
    asm volatile("ldmatrix.sync.aligned.m8n8.x4.shared.b16 {%0,%1,%2,%3}, [%4];"
        : "=r"(r0), "=r"(r1), "=r"(r2), "=r"(r3) : "r"(a));
}

__device__ __forceinline__ void mma_bf16(float c[4], const uint32_t a[4],
                                         uint32_t b0, uint32_t b1) {
    asm volatile("mma.sync.aligned.m16n8k16.row.col.f32.bf16.bf16.f32 "
        "{%0,%1,%2,%3}, {%4,%5,%6,%7}, {%8,%9}, {%0,%1,%2,%3};"
        : "+f"(c[0]), "+f"(c[1]), "+f"(c[2]), "+f"(c[3])
        : "r"(a[0]), "r"(a[1]), "r"(a[2]), "r"(a[3]), "r"(b0), "r"(b1));
}

__device__ __forceinline__ uint32_t pack_bf16(float a, float b) {
    return (uint32_t)__bfloat16_as_ushort(__float2bfloat16(a))
         | ((uint32_t)__bfloat16_as_ushort(__float2bfloat16(b)) << 16);
}

#define CPA16(sm, gp) asm volatile("cp.async.cg.shared.global [%0], [%1], 16;" :: "r"(sm), "l"(gp))
#define CP_COMMIT()   asm volatile("cp.async.commit_group;" ::: "memory")
#define CP_WAIT0()    asm volatile("cp.async.wait_group 0;" ::: "memory")
#define CP_WAIT1()    asm volatile("cp.async.wait_group 1;" ::: "memory")

// ---------------------------------------------------------------------------
// Segment starts (int32/int64 guide auto-detect)
// ---------------------------------------------------------------------------
__global__ void seg_kernel(const void* __restrict__ guide, int n, int* __restrict__ seg)
{
    int g = blockIdx.x * blockDim.x + threadIdx.x;
    if (g > BATCH) return;
    const unsigned long long* g64 = (const unsigned long long*)guide;
    const int*                g32 = (const int*)guide;
    bool is64 = (g64[(n >> 1) - 1] <= 511ull);
    int lo = 0, hi = n;
    while (lo < hi) {
        int mid = (lo + hi) >> 1;
        long long v = is64 ? (long long)g64[mid] : (long long)g32[mid];
        if (v < (long long)g) lo = mid + 1; else hi = mid;
    }
    seg[g] = lo;
}

// ---------------------------------------------------------------------------
// Copy cell -> out[:, EMB:EMB+D_CELL]
// ---------------------------------------------------------------------------
__global__ void copy_cell_kernel(const float4* __restrict__ cell, float4* __restrict__ out)
{
    int i = blockIdx.x * blockDim.x + threadIdx.x;
    if (i >= BATCH * (D_CELL / 4)) return;
    int b = i >> 8, j = i & 255;
    out[b * ((EMB + D_CELL) / 4) + (EMB / 4) + j] = cell[i];
}

// ---------------------------------------------------------------------------
// Fused split: all fp32->bf16(hi,lo) conversions in one sweep.
// Segments (in float4 units): Wc 262144 | Wq 262144 | Wo 262144 | Wv 65536 | cell 131072
// ---------------------------------------------------------------------------
__device__ __forceinline__ void split4(const float4* s, uint2* hi, uint2* lo, int i)
{
    float4 v = s[i];
    __nv_bfloat16 h0 = __float2bfloat16(v.x), h1 = __float2bfloat16(v.y);
    __nv_bfloat16 h2 = __float2bfloat16(v.z), h3 = __float2bfloat16(v.w);
    uint2 H, L;
    H.x = (uint32_t)__bfloat16_as_ushort(h0) | ((uint32_t)__bfloat16_as_ushort(h1) << 16);
    H.y = (uint32_t)__bfloat16_as_ushort(h2) | ((uint32_t)__bfloat16_as_ushort(h3) << 16);
    L.x = pack_bf16(v.x - __bfloat162float(h0), v.y - __bfloat162float(h1));
    L.y = pack_bf16(v.z - __bfloat162float(h2), v.w - __bfloat162float(h3));
    hi[i] = H; lo[i] = L;
}

__global__ __launch_bounds__(256)
void split_all(const float4* Wc, const float4* Wq, const float4* Wo,
               const float4* Wv, const float4* cell,
               uint2* wch, uint2* wcl, uint2* wqh, uint2* wql,
               uint2* woh, uint2* wol, uint2* wvh, uint2* wvl,
               uint2* ah, uint2* al)
{
    int i = blockIdx.x * 256 + threadIdx.x;
    if      (i < 262144)  split4(Wc, wch, wcl, i);
    else if (i < 524288)  split4(Wq, wqh, wql, i - 262144);
    else if (i < 786432)  split4(Wo, woh, wol, i - 524288);
    else if (i < 851968)  split4(Wv, wvh, wvl, i - 786432);
    else if (i < 983040)  split4(cell, ah, al, i - 851968);
}

// ---------------------------------------------------------------------------
// Wk transpose-split: out[h][n][d] = Wk[h*64+d][n], bf16 hi/lo
// ---------------------------------------------------------------------------
__global__ __launch_bounds__(256)
void splitT_wk(const float* __restrict__ Wk,
               __nv_bfloat16* __restrict__ oh, __nv_bfloat16* __restrict__ ol)
{
    __shared__ float tile[32][33];
    int h = blockIdx.z, nt = blockIdx.x, dt = blockIdx.y;
    int tx = threadIdx.x & 31, ty = threadIdx.x >> 5;
#pragma unroll
    for (int r = ty; r < 32; r += 8)
        tile[r][tx] = Wk[(long long)(h * 64 + dt * 32 + r) * D_DRUG + nt * 32 + tx];
    __syncthreads();
#pragma unroll
    for (int r = ty; r < 32; r += 8) {
        float v = tile[tx][r];
        __nv_bfloat16 hh = __float2bfloat16(v);
        long long o = (long long)h * (D_DRUG * HDIM) + (long long)(nt * 32 + r) * HDIM + dt * 32 + tx;
        oh[o] = hh;
        ol[o] = __float2bfloat16(v - __bfloat162float(hh));
    }
}

// ---------------------------------------------------------------------------
// Split-K reduce over [512,1024]: v = alpha*(sum_s part + bias)
// MODE 0: bf16 hi/lo out (ldc el).  MODE 1: fp32 out (ldc el).
// ---------------------------------------------------------------------------
template <int MODE>
__global__ __launch_bounds__(256)
void reduce_k(const float4* __restrict__ part, const float* __restrict__ bias,
              float* __restrict__ outf, __nv_bfloat16* __restrict__ oh,
              __nv_bfloat16* __restrict__ ol, int ldc, float alpha, int ns)
{
    int i = blockIdx.x * 256 + threadIdx.x;
    if (i >= BATCH * (EMB / 4)) return;
    int b = i >> 8, j = i & 255;
    float4 s = part[i];
    for (int k = 1; k < ns; k++) {
        float4 p = part[k * (BATCH * EMB / 4) + i];
        s.x += p.x; s.y += p.y; s.z += p.z; s.w += p.w;
    }
    int col = j * 4;
    float4 bb = *(const float4*)(bias + col);
    float vx = alpha * (s.x + bb.x), vy = alpha * (s.y + bb.y);
    float vz = alpha * (s.z + bb.z), vw = alpha * (s.w + bb.w);
    if (MODE == 1) {
        *(float4*)(outf + (long long)b * ldc + col) = make_float4(vx, vy, vz, vw);
    } else {
        __nv_bfloat16 h0 = __float2bfloat16(vx), h1 = __float2bfloat16(vy);
        __nv_bfloat16 h2 = __float2bfloat16(vz), h3 = __float2bfloat16(vw);
        uint2 H, L;
        H.x = (uint32_t)__bfloat16_as_ushort(h0) | ((uint32_t)__bfloat16_as_ushort(h1) << 16);
        H.y = (uint32_t)__bfloat16_as_ushort(h2) | ((uint32_t)__bfloat16_as_ushort(h3) << 16);
        L.x = pack_bf16(vx - __bfloat162float(h0), vy - __bfloat162float(h1));
        L.y = pack_bf16(vz - __bfloat162float(h2), vw - __bfloat162float(h3));
        *(uint2*)(oh + (long long)b * ldc + col) = H;
        *(uint2*)(ol + (long long)b * ldc + col) = L;
    }
}

// ---------------------------------------------------------------------------
// bf16x3 MMA GEMM with cp.async 2-stage pipeline + optional split-K.
//   C[M,N] = A[M,K]*W[N,K]^T  (3 products: Ah*Wh + Ah*Wl + Al*Wh, fp32 acc)
// blockIdx.z = zb*nks + zk; zb batches (stride sAz/sWz/sbz/sCz), zk K-slices.
// CTA 64x64, 128 thr. Smem 2 x 20480 (rows 64 x 80B per array).
// MODE 0: bf16 hi/lo split of alpha*(acc+bias).  MODE 1: fp32 alpha*(acc+bias).
// MODE 2: raw fp32 partial at Cf + zk*pstr + zb*sCz.
// ---------------------------------------------------------------------------
template <int MODE>
__global__ __launch_bounds__(128)
void mma_gemm3x(const __nv_bfloat16* __restrict__ Ah, const __nv_bfloat16* __restrict__ Al,
                int lda, long long sAz,
                const __nv_bfloat16* __restrict__ Wh, const __nv_bfloat16* __restrict__ Wl,
                int ldw, long long sWz,
                const float* __restrict__ bias, long long sbz,
                float* __restrict__ Cf,
                __nv_bfloat16* __restrict__ Ch, __nv_bfloat16* __restrict__ Cl,
                int ldc, long long sCz, float alpha, int Kslice, int nks, long long pstr)
{
    __shared__ __align__(16) char smraw[40960];

    int zb = blockIdx.z / nks, zk = blockIdx.z % nks;
    const __nv_bfloat16* Ah_ = Ah + (long long)zb * sAz + (long long)zk * Kslice;
    const __nv_bfloat16* Al_ = Al + (long long)zb * sAz + (long long)zk * Kslice;
    const __nv_bfloat16* Wh_ = Wh + (long long)zb * sWz + (long long)zk * Kslice;
    const __nv_bfloat16* Wl_ = Wl + (long long)zb * sWz + (long long)zk * Kslice;
    const float* bp = bias ? bias + (long long)zb * sbz : nullptr;
    long long coff = (MODE == 2) ? ((long long)zk * pstr + (long long)zb * sCz)
                                 : ((long long)zb * sCz);

    int tid = threadIdx.x, lane = tid & 31, warp = tid >> 5;
    int wm = warp >> 1, wn = warp & 1;
    int m0 = blockIdx.y * 64, n0 = blockIdx.x * 64;

    int lr0 = tid >> 2, lr1 = lr0 + 32;
    int lq  = (tid & 3) * 8;
    int lo0 = lr0 * 80 + (tid & 3) * 16;
    int lo1 = lr1 * 80 + (tid & 3) * 16;

    const __nv_bfloat16* pAh0 = Ah_ + (long long)(m0 + lr0) * lda + lq;
    const __nv_bfloat16* pAh1 = Ah_ + (long long)(m0 + lr1) * lda + lq;
    const __nv_bfloat16* pAl0 = Al_ + (long long)(m0 + lr0) * lda + lq;
    const __nv_bfloat16* pAl1 = Al_ + (long long)(m0 + lr1) * lda + lq;
    const __nv_bfloat16* pWh0 = Wh_ + (long long)(n0 + lr0) * ldw + lq;
    const __nv_bfloat16* pWh1 = Wh_ + (long long)(n0 + lr1) * ldw + lq;
    const __nv_bfloat16* pWl0 = Wl_ + (long long)(n0 + lr0) * ldw + lq;
    const __nv_bfloat16* pWl1 = Wl_ + (long long)(n0 + lr1) * ldw + lq;

    uint32_t smb = smem_u32(smraw);

    // async tile loader (one commit group = one tile)
    auto issue = [&](uint32_t so, int k0) {
        CPA16(smb + so + lo0,          (const char*)(pAh0 + k0));
        CPA16(smb + so + lo1,          (const char*)(pAh1 + k0));
        CPA16(smb + so + 5120  + lo0,  (const char*)(pAl0 + k0));
        CPA16(smb + so + 5120  + lo1,  (const char*)(pAl1 + k0));
        CPA16(smb + so + 10240 + lo0,  (const char*)(pWh0 + k0));
        CPA16(smb + so + 10240 + lo1,  (const char*)(pWh1 + k0));
        CPA16(smb + so + 15360 + lo0,  (const char*)(pWl0 + k0));
        CPA16(smb + so + 15360 + lo1,  (const char*)(pWl1 + k0));
        CP_COMMIT();
    };

    float acc[2][4][4];
#pragma unroll
    for (int s = 0; s < 2; s++)
#pragma unroll
        for (int nb = 0; nb < 4; nb++)
#pragma unroll
            for (int i = 0; i < 4; i++) acc[s][nb][i] = 0.f;

    uint32_t aBase = smb + (uint32_t)((wm * 32 + (lane & 15)) * 80 + ((lane >> 4) & 1) * 16);
    uint32_t bBase = smb + 10240u +
        (uint32_t)((wn * 32 + ((lane >> 4) & 1) * 8 + (lane & 7)) * 80 + ((lane >> 3) & 1) * 16);

    int NT = Kslice / 32;
    issue(0, 0);
    if (NT > 1) issue(20480, 32);

    for (int t = 0; t < NT; t++) {
        if (t + 1 < NT) { CP_WAIT1(); } else { CP_WAIT0(); }
        __syncthreads();

        uint32_t bufo = (uint32_t)(t & 1) * 20480u;
#pragma unroll
        for (int kk = 0; kk < 2; kk++) {
            uint32_t ah[2][4], alr[2][4];
#pragma unroll
            for (int s = 0; s < 2; s++) {
                uint32_t ad = aBase + bufo + (uint32_t)(s * 1280 + kk * 32);
                ldsm4(ah[s][0], ah[s][1], ah[s][2], ah[s][3], ad);
                ldsm4(alr[s][0], alr[s][1], alr[s][2], alr[s][3], ad + 5120u);
            }
            uint32_t bh[4][2], blr[4][2];
#pragma unroll
            for (int p = 0; p < 2; p++) {
                uint32_t bd = bBase + bufo + (uint32_t)(p * 1280 + kk * 32);
                ldsm4(bh[2*p][0], bh[2*p][1], bh[2*p+1][0], bh[2*p+1][1], bd);
                ldsm4(blr[2*p][0], blr[2*p][1], blr[2*p+1][0], blr[2*p+1][1], bd + 5120u);
            }
#pragma unroll
            for (int s = 0; s < 2; s++)
#pragma unroll
                for (int nb = 0; nb < 4; nb++) {
                    mma_bf16(acc[s][nb], ah[s],  bh[nb][0],  bh[nb][1]);
                    mma_bf16(acc[s][nb], ah[s],  blr[nb][0], blr[nb][1]);
                    mma_bf16(acc[s][nb], alr[s], bh[nb][0],  bh[nb][1]);
                }
        }
        __syncthreads();   // everyone done reading stage t before it is refilled
        if (t + 2 < NT) issue((uint32_t)(t & 1) * 20480u, (t + 2) * 32);
    }

    int erow = lane >> 2;
    int ecol = (lane & 3) * 2;
#pragma unroll
    for (int s = 0; s < 2; s++) {
        int r0 = m0 + wm * 32 + s * 16 + erow;
#pragma unroll
        for (int nb = 0; nb < 4; nb++) {
            int col = n0 + wn * 32 + nb * 8 + ecol;
            if (MODE == 2) {
                *(float2*)(Cf + coff + (long long)r0 * ldc + col)
                    = make_float2(acc[s][nb][0], acc[s][nb][1]);
                *(float2*)(Cf + coff + (long long)(r0 + 8) * ldc + col)
                    = make_float2(acc[s][nb][2], acc[s][nb][3]);
            } else {
                float b0 = bp ? bp[col] : 0.f;
                float b1 = bp ? bp[col + 1] : 0.f;
                float v00 = alpha * (acc[s][nb][0] + b0);
                float v01 = alpha * (acc[s][nb][1] + b1);
                float v10 = alpha * (acc[s][nb][2] + b0);
                float v11 = alpha * (acc[s][nb][3] + b1);
                if (MODE == 1) {
                    *(float2*)(Cf + coff + (long long)r0 * ldc + col)       = make_float2(v00, v01);
                    *(float2*)(Cf + coff + (long long)(r0 + 8) * ldc + col) = make_float2(v10, v11);
                } else {
                    __nv_bfloat16 h00 = __float2bfloat16(v00), h01 = __float2bfloat16(v01);
                    __nv_bfloat16 h10 = __float2bfloat16(v10), h11 = __float2bfloat16(v11);
                    uint32_t ph0 = (uint32_t)__bfloat16_as_ushort(h00)
                                 | ((uint32_t)__bfloat16_as_ushort(h01) << 16);
                    uint32_t ph1 = (uint32_t)__bfloat16_as_ushort(h10)
                                 | ((uint32_t)__bfloat16_as_ushort(h11) << 16);
                    uint32_t pl0 = pack_bf16(v00 - __bfloat162float(h00), v01 - __bfloat162float(h01));
                    uint32_t pl1 = pack_bf16(v10 - __bfloat162float(h10), v11 - __bfloat162float(h11));
                    *(uint32_t*)(Ch + coff + (long long)r0 * ldc + col)       = ph0;
                    *(uint32_t*)(Ch + coff + (long long)(r0 + 8) * ldc + col) = ph1;
                    *(uint32_t*)(Cl + coff + (long long)r0 * ldc + col)       = pl0;
                    *(uint32_t*)(Cl + coff + (long long)(r0 + 8) * ldc + col) = pl1;
                }
            }
        }
    }
}

// ---------------------------------------------------------------------------
// Fused attention (unchanged): scores -> softmax -> xa (bf16 hi/lo)
// ---------------------------------------------------------------------------
__global__ __launch_bounds__(256)
void attn_kernel(const float* __restrict__ x,
                 const float* __restrict__ qk,
                 const int*   __restrict__ seg,
                 __nv_bfloat16* __restrict__ xah,
                 __nv_bfloat16* __restrict__ xal)
{
    __shared__ float qks[16 * 260];
    __shared__ float xs [16 * 260];
    __shared__ float sc [16 * 132];

    int b = blockIdx.x;
    int t = threadIdx.x;
    int s0 = seg[b];
    int len = seg[b + 1] - s0;
    if (len > MAXLEN) len = MAXLEN;

    const float4* qk4 = (const float4*)(qk + (long long)b * (NHEAD * D_DRUG));
#pragma unroll
    for (int r = 0; r < 4; r++) {
        int idx = t + r * 256;
        int h = idx >> 6, jj = idx & 63;
        *(float4*)&qks[h * 260 + jj * 4] = qk4[idx];
    }
    __syncthreads();

    int hh = t >> 4, mm = t & 15;
    for (int m0 = 0; m0 < len; m0 += 16) {
        int nm = len - m0; if (nm > 16) nm = 16;
#pragma unroll
        for (int r = 0; r < 4; r++) {
            int idx = t + r * 256;
            int row = idx >> 6, jj = idx & 63;
            if (row < nm)
                *(float4*)&xs[row * 260 + jj * 4] =
                    *(const float4*)(x + (long long)(s0 + m0 + row) * D_DRUG + jj * 4);
        }
        __syncthreads();
        if (mm < nm) {
            const float* qp = &qks[hh * 260];
            const float* xp = &xs[mm * 260];
            F2U acc0, acc1;
            acc0.f = make_float2(0.f, 0.f);
            acc1.f = make_float2(0.f, 0.f);
#pragma unroll
            for (int j = 0; j < 256; j += 8) {
                float4 a0 = *(const float4*)(qp + j);
                float4 b0 = *(const float4*)(xp + j);
                float4 a1 = *(const float4*)(qp + j + 4);
                float4 b1 = *(const float4*)(xp + j + 4);
                F2U aa, bb;
                aa.f = make_float2(a0.x, a0.y); bb.f = make_float2(b0.x, b0.y); fma2(acc0, aa, bb);
                aa.f = make_float2(a0.z, a0.w); bb.f = make_float2(b0.z, b0.w); fma2(acc1, aa, bb);
                aa.f = make_float2(a1.x, a1.y); bb.f = make_float2(b1.x, b1.y); fma2(acc0, aa, bb);
                aa.f = make_float2(a1.z, a1.w); bb.f = make_float2(b1.z, b1.w); fma2(acc1, aa, bb);
            }
            sc[hh * 132 + m0 + mm] = acc0.f.x + acc0.f.y + acc1.f.x + acc1.f.y;
        }
        __syncthreads();
    }

    int w = t >> 5, lane = t & 31;
#pragma unroll
    for (int hq = 0; hq < 2; hq++) {
        int h = w * 2 + hq;
        float mx = -3.0e38f;
        for (int m = lane; m < len; m += 32) mx = fmaxf(mx, sc[h * 132 + m]);
#pragma unroll
        for (int o = 16; o; o >>= 1) mx = fmaxf(mx, __shfl_xor_sync(0xffffffffu, mx, o));
        float sum = 0.f;
        for (int m = lane; m < len; m += 32) {
            float e = __expf(sc[h * 132 + m] - mx);
            sc[h * 132 + m] = e;
            sum += e;
        }
#pragma unroll
        for (int o = 16; o; o >>= 1) sum += __shfl_xor_sync(0xffffffffu, sum, o);
        float inv = 1.0f / sum;
        for (int m = lane; m < len; m += 32) sc[h * 132 + m] *= inv;
    }
    __syncthreads();

    int h = t >> 4;
    int j0 = (t & 15) * 16;
    F2U acc[8];
#pragma unroll
    for (int i = 0; i < 8; i++) acc[i].f = make_float2(0.f, 0.f);
    for (int m = 0; m < len; m++) {
        float a = sc[h * 132 + m];
        F2U ad; ad.f = make_float2(a, a);
        const float4* xr = (const float4*)(x + (long long)(s0 + m) * D_DRUG + j0);
#pragma unroll
        for (int r = 0; r < 4; r++) {
            float4 v = xr[r];
            F2U b0, b1;
            b0.f = make_float2(v.x, v.y);
            b1.f = make_float2(v.z, v.w);
            fma2(acc[2 * r], ad, b0);
            fma2(acc[2 * r + 1], ad, b1);
        }
    }
    long long base = (long long)b * (NHEAD * D_DRUG) + h * D_DRUG + j0;
#pragma unroll
    for (int i = 0; i < 8; i++) {
        float va = acc[i].f.x, vb = acc[i].f.y;
        __nv_bfloat16 ha = __float2bfloat16(va), hb = __float2bfloat16(vb);
        uint32_t ph = (uint32_t)__bfloat16_as_ushort(ha)
                    | ((uint32_t)__bfloat16_as_ushort(hb) << 16);
        uint32_t pl = pack_bf16(va - __bfloat162float(ha), vb - __bfloat162float(hb));
        *(uint32_t*)(xah + base + i * 2) = ph;
        *(uint32_t*)(xal + base + i * 2) = pl;
    }
}

// ---------------------------------------------------------------------------
// Launch
// ---------------------------------------------------------------------------
extern "C" void kernel_launch(void* const* d_in, const int* in_sizes, int n_in,
                              void* d_out, int out_size)
{
    const float* x_nodes = (const float*)d_in[0];
    const float* cell    = (const float*)d_in[1];
    const float* Wq      = (const float*)d_in[2];
    const float* bq      = (const float*)d_in[3];
    const float* Wk      = (const float*)d_in[4];
    /* bk cancels in softmax */
    const float* Wv      = (const float*)d_in[6];
    const float* bv      = (const float*)d_in[7];
    const float* Wo      = (const float*)d_in[8];
    const float* bo      = (const float*)d_in[9];
    const float* Wc      = (const float*)d_in[10];
    const float* bc      = (const float*)d_in[11];
    const void*  guide   = d_in[12];
    float*       out     = (float*)d_out;

    int N = in_sizes[12];

    float *qkp, *part; int* seg;
    __nv_bfloat16 *a0h, *a0l, *a1h, *a1l, *xah, *xal;
    __nv_bfloat16 *wch, *wcl, *wqh, *wql, *woh, *wol, *wvh, *wvl, *wkth, *wktl;
    cudaGetSymbolAddress((void**)&qkp,  g_qk);
    cudaGetSymbolAddress((void**)&part, g_part);
    cudaGetSymbolAddress((void**)&seg,  g_seg);
    cudaGetSymbolAddress((void**)&a0h,  g_a0h);
    cudaGetSymbolAddress((void**)&a0l,  g_a0l);
    cudaGetSymbolAddress((void**)&a1h,  g_a1h);
    cudaGetSymbolAddress((void**)&a1l,  g_a1l);
    cudaGetSymbolAddress((void**)&xah,  g_xah);
    cudaGetSymbolAddress((void**)&xal,  g_xal);
    cudaGetSymbolAddress((void**)&wch,  g_wch);
    cudaGetSymbolAddress((void**)&wcl,  g_wcl);
    cudaGetSymbolAddress((void**)&wqh,  g_wqh);
    cudaGetSymbolAddress((void**)&wql,  g_wql);
    cudaGetSymbolAddress((void**)&woh,  g_woh);
    cudaGetSymbolAddress((void**)&wol,  g_wol);
    cudaGetSymbolAddress((void**)&wvh,  g_wvh);
    cudaGetSymbolAddress((void**)&wvl,  g_wvl);
    cudaGetSymbolAddress((void**)&wkth, g_wkth);
    cudaGetSymbolAddress((void**)&wktl, g_wktl);

    const long long PSTR = (long long)BATCH * EMB;   // partial slice stride (elements)

    // prep
    seg_kernel<<<3, 256>>>(guide, N, seg);
    copy_cell_kernel<<<512, 256>>>((const float4*)cell, (float4*)out);
    split_all<<<3840, 256>>>((const float4*)Wc, (const float4*)Wq, (const float4*)Wo,
                             (const float4*)Wv, (const float4*)cell,
                             (uint2*)wch, (uint2*)wcl, (uint2*)wqh, (uint2*)wql,
                             (uint2*)woh, (uint2*)wol, (uint2*)wvh, (uint2*)wvl,
                             (uint2*)a0h, (uint2*)a0l);
    splitT_wk<<<dim3(8, 2, 16), 256>>>(Wk, wkth, wktl);

    // G1: cq = cell @ Wc^T + bc    (split-K=4 -> partials -> bf16 hi/lo a1)
    mma_gemm3x<2><<<dim3(16, 8, 4), 128>>>(
        a0h, a0l, D_CELL, 0, wch, wcl, D_CELL, 0, nullptr, 0,
        part, nullptr, nullptr, EMB, 0, 1.0f, 256, 4, PSTR);
    reduce_k<0><<<512, 256>>>((const float4*)part, bc, nullptr, a1h, a1l, EMB, 1.0f, 4);

    // G2: q = (cq @ Wq^T + bq) * 0.125  -> bf16 hi/lo a0
    mma_gemm3x<2><<<dim3(16, 8, 4), 128>>>(
        a1h, a1l, EMB, 0, wqh, wql, EMB, 0, nullptr, 0,
        part, nullptr, nullptr, EMB, 0, 1.0f, 256, 4, PSTR);
    reduce_k<0><<<512, 256>>>((const float4*)part, bq, nullptr, a0h, a0l, EMB, 0.125f, 4);

    // qk[b,h,:] = q[b,h,:] @ WkT_h   (16 heads, K=64, no split)
    mma_gemm3x<1><<<dim3(4, 8, 16), 128>>>(
        a0h, a0l, EMB, HDIM, wkth, wktl, HDIM, (long long)D_DRUG * HDIM, nullptr, 0,
        qkp, nullptr, nullptr, NHEAD * D_DRUG, D_DRUG, 1.0f, HDIM, 1, 0);

    // fused scores -> softmax -> xa (hi/lo)
    attn_kernel<<<512, 256>>>(x_nodes, qkp, seg, xah, xal);

    // vv: op[b, h*64+:] = xa[b,h,:] @ Wv_h^T + bv  (16 heads x split-K=2)
    mma_gemm3x<2><<<dim3(1, 8, 32), 128>>>(
        xah, xal, NHEAD * D_DRUG, D_DRUG, wvh, wvl, D_DRUG, (long long)HDIM * D_DRUG,
        nullptr, 0,
        part, nullptr, nullptr, EMB, HDIM, 1.0f, 128, 2, PSTR);
    reduce_k<0><<<512, 256>>>((const float4*)part, bv, nullptr, a1h, a1l, EMB, 1.0f, 2);

    // G3: out[:, :1024] = op @ Wo^T + bo   (split-K=4 -> fp32 strided)
    mma_gemm3x<2><<<dim3(16, 8, 4), 128>>>(
        a1h, a1l, EMB, 0, woh, wol, EMB, 0, nullptr, 0,
        part, nullptr, nullptr, EMB, 0, 1.0f, 256, 4, PSTR);
    reduce_k<1><<<512, 256>>>((const float4*)part, bo, out, nullptr, nullptr,
                              EMB + D_CELL, 1.0f, 4);

    (void)n_in; (void)out_size;
}

// round 7
// speedup vs baseline: 1.3120x; 1.0118x over previous
#include <cuda_runtime.h>
#include <cuda_bf16.h>
#include <cstdint>

// ---------------------------------------------------------------------------
// Problem constants
// ---------------------------------------------------------------------------
#define BATCH   512
#define MAXLEN  128
#define D_DRUG  256
#define D_CELL  1024
#define NHEAD   16
#define HDIM    64
#define EMB     1024   // NHEAD*HDIM

// ---------------------------------------------------------------------------
// Scratch (device globals)
// ---------------------------------------------------------------------------
__device__ float g_qk  [BATCH * NHEAD * D_DRUG];   // q folded through Wk (fp32)
__device__ float g_part[4 * BATCH * EMB];          // split-K partials (8 MB)
__device__ int   g_seg [BATCH + 1];

__device__ __nv_bfloat16 g_a0h[BATCH * EMB],   g_a0l[BATCH * EMB];    // cell, then q
__device__ __nv_bfloat16 g_a1h[BATCH * EMB],   g_a1l[BATCH * EMB];    // cq, then op
__device__ __nv_bfloat16 g_xah[BATCH * NHEAD * D_DRUG], g_xal[BATCH * NHEAD * D_DRUG];
__device__ __nv_bfloat16 g_wch[EMB * D_CELL],  g_wcl[EMB * D_CELL];
__device__ __nv_bfloat16 g_wqh[EMB * EMB],     g_wql[EMB * EMB];
__device__ __nv_bfloat16 g_woh[EMB * EMB],     g_wol[EMB * EMB];
__device__ __nv_bfloat16 g_wvh[EMB * D_DRUG],  g_wvl[EMB * D_DRUG];
__device__ __nv_bfloat16 g_wkth[NHEAD * D_DRUG * HDIM], g_wktl[NHEAD * D_DRUG * HDIM];

// ---------------------------------------------------------------------------
// Helpers
// ---------------------------------------------------------------------------
union F2U { float2 f; unsigned long long u; };
__device__ __forceinline__ void fma2(F2U &c, F2U a, F2U b) {
    asm("fma.rn.f32x2 %0, %1, %2, %0;" : "+l"(c.u) : "l"(a.u), "l"(b.u));
}

__device__ __forceinline__ uint32_t smem_u32(const void* p) {
    uint32_t a;
    asm("{ .reg .u64 t; cvta.to.shared.u64 t, %1; cvt.u32.u64 %0, t; }" : "=r"(a) : "l"(p));
    return a;
}

__device__ __forceinline__ void ldsm4(uint32_t &r0, uint32_t &r1, uint32_t &r2, uint32_t &r3,
                                      uint32_t a) {
    asm volatile("ldmatrix.sync.aligned.m8n8.x4.shared.b16 {%0,%1,%2,%3}, [%4];"
        : "=r"(r0), "=r"(r1), "=r"(r2), "=r"(r3) : "r"(a));
}

__device__ __forceinline__ void mma_bf16(float c[4], const uint32_t a[4],
                                         uint32_t b0, uint32_t b1) {
    asm volatile("mma.sync.aligned.m16n8k16.row.col.f32.bf16.bf16.f32 "
        "{%0,%1,%2,%3}, {%4,%5,%6,%7}, {%8,%9}, {%0,%1,%2,%3};"
        : "+f"(c[0]), "+f"(c[1]), "+f"(c[2]), "+f"(c[3])
        : "r"(a[0]), "r"(a[1]), "r"(a[2]), "r"(a[3]), "r"(b0), "r"(b1));
}

__device__ __forceinline__ uint32_t pack_bf16(float a, float b) {
    return (uint32_t)__bfloat16_as_ushort(__float2bfloat16(a))
         | ((uint32_t)__bfloat16_as_ushort(__float2bfloat16(b)) << 16);
}

#define CPA16(sm, gp) asm volatile("cp.async.cg.shared.global [%0], [%1], 16;" :: "r"(sm), "l"(gp))
#define CP_COMMIT()   asm volatile("cp.async.commit_group;" ::: "memory")
#define CP_WAIT0()    asm volatile("cp.async.wait_group 0;" ::: "memory")
#define CP_WAIT1()    asm volatile("cp.async.wait_group 1;" ::: "memory")

// ---------------------------------------------------------------------------
// Fused prep kernel: block-range dispatch.
//   [0,3840)      split_all  (Wc|Wq|Wo|Wv|cell fp32 -> bf16 hi/lo)
//   [3840,4096)   splitT_wk  (Wk per-head transpose-split)
//   [4096,4099)   seg        (segment starts via binary search)
//   [4099,4611)   copy_cell  (cell -> out right half)
// ---------------------------------------------------------------------------
__device__ __forceinline__ void split4(const float4* s, uint2* hi, uint2* lo, int i)
{
    float4 v = s[i];
    __nv_bfloat16 h0 = __float2bfloat16(v.x), h1 = __float2bfloat16(v.y);
    __nv_bfloat16 h2 = __float2bfloat16(v.z), h3 = __float2bfloat16(v.w);
    uint2 H, L;
    H.x = (uint32_t)__bfloat16_as_ushort(h0) | ((uint32_t)__bfloat16_as_ushort(h1) << 16);
    H.y = (uint32_t)__bfloat16_as_ushort(h2) | ((uint32_t)__bfloat16_as_ushort(h3) << 16);
    L.x = pack_bf16(v.x - __bfloat162float(h0), v.y - __bfloat162float(h1));
    L.y = pack_bf16(v.z - __bfloat162float(h2), v.w - __bfloat162float(h3));
    hi[i] = H; lo[i] = L;
}

__global__ __launch_bounds__(256)
void prep_kernel(const float4* Wc, const float4* Wq, const float4* Wo,
                 const float4* Wv, const float4* cell, const float* Wk,
                 const void* guide, int n,
                 uint2* wch, uint2* wcl, uint2* wqh, uint2* wql,
                 uint2* woh, uint2* wol, uint2* wvh, uint2* wvl,
                 uint2* ah, uint2* al,
                 __nv_bfloat16* wkth, __nv_bfloat16* wktl,
                 int* seg, float4* outp)
{
    __shared__ float tile[32][33];
    int blk = blockIdx.x, t = threadIdx.x;

    if (blk < 3840) {
        int i = blk * 256 + t;
        if      (i < 262144)  split4(Wc, wch, wcl, i);
        else if (i < 524288)  split4(Wq, wqh, wql, i - 262144);
        else if (i < 786432)  split4(Wo, woh, wol, i - 524288);
        else if (i < 851968)  split4(Wv, wvh, wvl, i - 786432);
        else if (i < 983040)  split4(cell, ah, al, i - 851968);
    } else if (blk < 4096) {
        int b2 = blk - 3840;
        int nt = b2 & 7, dt = (b2 >> 3) & 1, h = b2 >> 4;
        int tx = t & 31, ty = t >> 5;
#pragma unroll
        for (int r = ty; r < 32; r += 8)
            tile[r][tx] = Wk[(long long)(h * 64 + dt * 32 + r) * D_DRUG + nt * 32 + tx];
        __syncthreads();
#pragma unroll
        for (int r = ty; r < 32; r += 8) {
            float v = tile[tx][r];
            __nv_bfloat16 hh = __float2bfloat16(v);
            long long o = (long long)h * (D_DRUG * HDIM)
                        + (long long)(nt * 32 + r) * HDIM + dt * 32 + tx;
            wkth[o] = hh;
            wktl[o] = __float2bfloat16(v - __bfloat162float(hh));
        }
    } else if (blk < 4099) {
        int g = (blk - 4096) * 256 + t;
        if (g <= BATCH) {
            const unsigned long long* g64 = (const unsigned long long*)guide;
            const int*                g32 = (const int*)guide;
            bool is64 = (g64[(n >> 1) - 1] <= 511ull);
            int lo2 = 0, hi2 = n;
            while (lo2 < hi2) {
                int mid = (lo2 + hi2) >> 1;
                long long v = is64 ? (long long)g64[mid] : (long long)g32[mid];
                if (v < (long long)g) lo2 = mid + 1; else hi2 = mid;
            }
            seg[g] = lo2;
        }
    } else {
        int i = (blk - 4099) * 256 + t;
        if (i < BATCH * (D_CELL / 4)) {
            int b = i >> 8, j = i & 255;
            outp[b * ((EMB + D_CELL) / 4) + (EMB / 4) + j] = cell[i];   // FIX: plain i
        }
    }
}

// ---------------------------------------------------------------------------
// Split-K reduce over [512,1024]: v = alpha*(sum_s part + bias)
// MODE 0: bf16 hi/lo out.  MODE 1: fp32 out.
// ---------------------------------------------------------------------------
template <int MODE>
__global__ __launch_bounds__(256)
void reduce_k(const float4* __restrict__ part, const float* __restrict__ bias,
              float* __restrict__ outf, __nv_bfloat16* __restrict__ oh,
              __nv_bfloat16* __restrict__ ol, int ldc, float alpha, int ns)
{
    int i = blockIdx.x * 256 + threadIdx.x;
    if (i >= BATCH * (EMB / 4)) return;
    int b = i >> 8, j = i & 255;
    float4 s = part[i];
    for (int k = 1; k < ns; k++) {
        float4 p = part[k * (BATCH * EMB / 4) + i];
        s.x += p.x; s.y += p.y; s.z += p.z; s.w += p.w;
    }
    int col = j * 4;
    float4 bb = *(const float4*)(bias + col);
    float vx = alpha * (s.x + bb.x), vy = alpha * (s.y + bb.y);
    float vz = alpha * (s.z + bb.z), vw = alpha * (s.w + bb.w);
    if (MODE == 1) {
        *(float4*)(outf + (long long)b * ldc + col) = make_float4(vx, vy, vz, vw);
    } else {
        __nv_bfloat16 h0 = __float2bfloat16(vx), h1 = __float2bfloat16(vy);
        __nv_bfloat16 h2 = __float2bfloat16(vz), h3 = __float2bfloat16(vw);
        uint2 H, L;
        H.x = (uint32_t)__bfloat16_as_ushort(h0) | ((uint32_t)__bfloat16_as_ushort(h1) << 16);
        H.y = (uint32_t)__bfloat16_as_ushort(h2) | ((uint32_t)__bfloat16_as_ushort(h3) << 16);
        L.x = pack_bf16(vx - __bfloat162float(h0), vy - __bfloat162float(h1));
        L.y = pack_bf16(vz - __bfloat162float(h2), vw - __bfloat162float(h3));
        *(uint2*)(oh + (long long)b * ldc + col) = H;
        *(uint2*)(ol + (long long)b * ldc + col) = L;
    }
}

// ---------------------------------------------------------------------------
// bf16x3 MMA GEMM, 256 threads (8 warps, 2x4 grid of 32x16 warp tiles),
// cp.async 2-stage pipeline, optional split-K.
//   C[M,N] = A[M,K]*W[N,K]^T    (Ah*Wh + Ah*Wl + Al*Wh, fp32 accum)
// blockIdx.z = zb*nks + zk.
// MODE 1: fp32 alpha*(acc+bias).  MODE 2: raw fp32 partial (zk-strided).
// ---------------------------------------------------------------------------
template <int MODE>
__global__ __launch_bounds__(256)
void mma_gemm3x(const __nv_bfloat16* __restrict__ Ah, const __nv_bfloat16* __restrict__ Al,
                int lda, long long sAz,
                const __nv_bfloat16* __restrict__ Wh, const __nv_bfloat16* __restrict__ Wl,
                int ldw, long long sWz,
                const float* __restrict__ bias, long long sbz,
                float* __restrict__ Cf,
                int ldc, long long sCz, float alpha, int Kslice, int nks, long long pstr)
{
    __shared__ __align__(16) char smraw[40960];

    int zb = blockIdx.z / nks, zk = blockIdx.z % nks;
    const __nv_bfloat16* Ah_ = Ah + (long long)zb * sAz + (long long)zk * Kslice;
    const __nv_bfloat16* Al_ = Al + (long long)zb * sAz + (long long)zk * Kslice;
    const __nv_bfloat16* Wh_ = Wh + (long long)zb * sWz + (long long)zk * Kslice;
    const __nv_bfloat16* Wl_ = Wl + (long long)zb * sWz + (long long)zk * Kslice;
    const float* bp = bias ? bias + (long long)zb * sbz : nullptr;
    long long coff = (MODE == 2) ? ((long long)zk * pstr + (long long)zb * sCz)
                                 : ((long long)zb * sCz);

    int tid = threadIdx.x, lane = tid & 31, warp = tid >> 5;
    int wm = warp >> 2, wn = warp & 3;            // 2 x 4 warp grid
    int m0 = blockIdx.y * 64, n0 = blockIdx.x * 64;

    // loader: each thread loads ONE 16B chunk per array per tile
    int lr = tid >> 2;                  // row 0..63
    int lq = (tid & 3) * 8;             // k element
    int lo = lr * 80 + (tid & 3) * 16;  // smem byte offset

    const __nv_bfloat16* pAh = Ah_ + (long long)(m0 + lr) * lda + lq;
    const __nv_bfloat16* pAl = Al_ + (long long)(m0 + lr) * lda + lq;
    const __nv_bfloat16* pWh = Wh_ + (long long)(n0 + lr) * ldw + lq;
    const __nv_bfloat16* pWl = Wl_ + (long long)(n0 + lr) * ldw + lq;

    uint32_t smb = smem_u32(smraw);

    auto issue = [&](uint32_t so, int k0) {
        CPA16(smb + so + lo,          (const char*)(pAh + k0));
        CPA16(smb + so + 5120  + lo,  (const char*)(pAl + k0));
        CPA16(smb + so + 10240 + lo,  (const char*)(pWh + k0));
        CPA16(smb + so + 15360 + lo,  (const char*)(pWl + k0));
        CP_COMMIT();
    };

    float acc[2][2][4];
#pragma unroll
    for (int s = 0; s < 2; s++)
#pragma unroll
        for (int nb = 0; nb < 2; nb++)
#pragma unroll
            for (int i = 0; i < 4; i++) acc[s][nb][i] = 0.f;

    // A frag: row = wm*32 + s*16 + (lane&15), k-half = (lane>>4)&1
    uint32_t aBase = smb + (uint32_t)((wm * 32 + (lane & 15)) * 80 + ((lane >> 4) & 1) * 16);
    // B frag: row = wn*16 + ((lane>>4)&1)*8 + (lane&7), k-half = (lane>>3)&1
    uint32_t bBase = smb + 10240u +
        (uint32_t)((wn * 16 + ((lane >> 4) & 1) * 8 + (lane & 7)) * 80 + ((lane >> 3) & 1) * 16);

    int NT = Kslice / 32;
    issue(0, 0);
    if (NT > 1) issue(20480, 32);

    for (int t = 0; t < NT; t++) {
        if (t + 1 < NT) { CP_WAIT1(); } else { CP_WAIT0(); }
        __syncthreads();

        uint32_t bufo = (uint32_t)(t & 1) * 20480u;
#pragma unroll
        for (int kk = 0; kk < 2; kk++) {
            uint32_t ah[2][4], alr[2][4];
#pragma unroll
            for (int s = 0; s < 2; s++) {
                uint32_t ad = aBase + bufo + (uint32_t)(s * 1280 + kk * 32);
                ldsm4(ah[s][0], ah[s][1], ah[s][2], ah[s][3], ad);
                ldsm4(alr[s][0], alr[s][1], alr[s][2], alr[s][3], ad + 5120u);
            }
            uint32_t bh[2][2], blr[2][2];
            {
                uint32_t bd = bBase + bufo + (uint32_t)(kk * 32);
                ldsm4(bh[0][0], bh[0][1], bh[1][0], bh[1][1], bd);
                ldsm4(blr[0][0], blr[0][1], blr[1][0], blr[1][1], bd + 5120u);
            }
#pragma unroll
            for (int s = 0; s < 2; s++)
#pragma unroll
                for (int nb = 0; nb < 2; nb++) {
                    mma_bf16(acc[s][nb], ah[s],  bh[nb][0],  bh[nb][1]);
                    mma_bf16(acc[s][nb], ah[s],  blr[nb][0], blr[nb][1]);
                    mma_bf16(acc[s][nb], alr[s], bh[nb][0],  bh[nb][1]);
                }
        }
        __syncthreads();
        if (t + 2 < NT) issue((uint32_t)(t & 1) * 20480u, (t + 2) * 32);
    }

    int erow = lane >> 2;
    int ecol = (lane & 3) * 2;
#pragma unroll
    for (int s = 0; s < 2; s++) {
        int r0 = m0 + wm * 32 + s * 16 + erow;
#pragma unroll
        for (int nb = 0; nb < 2; nb++) {
            int col = n0 + wn * 16 + nb * 8 + ecol;
            if (MODE == 2) {
                *(float2*)(Cf + coff + (long long)r0 * ldc + col)
                    = make_float2(acc[s][nb][0], acc[s][nb][1]);
                *(float2*)(Cf + coff + (long long)(r0 + 8) * ldc + col)
                    = make_float2(acc[s][nb][2], acc[s][nb][3]);
            } else {
                float b0 = bp ? bp[col] : 0.f;
                float b1 = bp ? bp[col + 1] : 0.f;
                *(float2*)(Cf + coff + (long long)r0 * ldc + col)
                    = make_float2(alpha * (acc[s][nb][0] + b0), alpha * (acc[s][nb][1] + b1));
                *(float2*)(Cf + coff + (long long)(r0 + 8) * ldc + col)
                    = make_float2(alpha * (acc[s][nb][2] + b0), alpha * (acc[s][nb][3] + b1));
            }
        }
    }
}

// ---------------------------------------------------------------------------
// Fused attention: scores -> softmax -> xa (bf16 hi/lo)
// ---------------------------------------------------------------------------
__global__ __launch_bounds__(256)
void attn_kernel(const float* __restrict__ x,
                 const float* __restrict__ qk,
                 const int*   __restrict__ seg,
                 __nv_bfloat16* __restrict__ xah,
                 __nv_bfloat16* __restrict__ xal)
{
    __shared__ float qks[16 * 260];
    __shared__ float xs [16 * 260];
    __shared__ float sc [16 * 132];

    int b = blockIdx.x;
    int t = threadIdx.x;
    int s0 = seg[b];
    int len = seg[b + 1] - s0;
    if (len > MAXLEN) len = MAXLEN;

    const float4* qk4 = (const float4*)(qk + (long long)b * (NHEAD * D_DRUG));
#pragma unroll
    for (int r = 0; r < 4; r++) {
        int idx = t + r * 256;
        int h = idx >> 6, jj = idx & 63;
        *(float4*)&qks[h * 260 + jj * 4] = qk4[idx];
    }
    __syncthreads();

    int hh = t >> 4, mm = t & 15;
    for (int m0 = 0; m0 < len; m0 += 16) {
        int nm = len - m0; if (nm > 16) nm = 16;
#pragma unroll
        for (int r = 0; r < 4; r++) {
            int idx = t + r * 256;
            int row = idx >> 6, jj = idx & 63;
            if (row < nm)
                *(float4*)&xs[row * 260 + jj * 4] =
                    *(const float4*)(x + (long long)(s0 + m0 + row) * D_DRUG + jj * 4);
        }
        __syncthreads();
        if (mm < nm) {
            const float* qp = &qks[hh * 260];
            const float* xp = &xs[mm * 260];
            F2U acc0, acc1;
            acc0.f = make_float2(0.f, 0.f);
            acc1.f = make_float2(0.f, 0.f);
#pragma unroll
            for (int j = 0; j < 256; j += 8) {
                float4 a0 = *(const float4*)(qp + j);
                float4 b0 = *(const float4*)(xp + j);
                float4 a1 = *(const float4*)(qp + j + 4);
                float4 b1 = *(const float4*)(xp + j + 4);
                F2U aa, bb;
                aa.f = make_float2(a0.x, a0.y); bb.f = make_float2(b0.x, b0.y); fma2(acc0, aa, bb);
                aa.f = make_float2(a0.z, a0.w); bb.f = make_float2(b0.z, b0.w); fma2(acc1, aa, bb);
                aa.f = make_float2(a1.x, a1.y); bb.f = make_float2(b1.x, b1.y); fma2(acc0, aa, bb);
                aa.f = make_float2(a1.z, a1.w); bb.f = make_float2(b1.z, b1.w); fma2(acc1, aa, bb);
            }
            sc[hh * 132 + m0 + mm] = acc0.f.x + acc0.f.y + acc1.f.x + acc1.f.y;
        }
        __syncthreads();
    }

    int w = t >> 5, lane = t & 31;
#pragma unroll
    for (int hq = 0; hq < 2; hq++) {
        int h = w * 2 + hq;
        float mx = -3.0e38f;
        for (int m = lane; m < len; m += 32) mx = fmaxf(mx, sc[h * 132 + m]);
#pragma unroll
        for (int o = 16; o; o >>= 1) mx = fmaxf(mx, __shfl_xor_sync(0xffffffffu, mx, o));
        float sum = 0.f;
        for (int m = lane; m < len; m += 32) {
            float e = __expf(sc[h * 132 + m] - mx);
            sc[h * 132 + m] = e;
            sum += e;
        }
#pragma unroll
        for (int o = 16; o; o >>= 1) sum += __shfl_xor_sync(0xffffffffu, sum, o);
        float inv = 1.0f / sum;
        for (int m = lane; m < len; m += 32) sc[h * 132 + m] *= inv;
    }
    __syncthreads();

    int h = t >> 4;
    int j0 = (t & 15) * 16;
    F2U acc[8];
#pragma unroll
    for (int i = 0; i < 8; i++) acc[i].f = make_float2(0.f, 0.f);
    for (int m = 0; m < len; m++) {
        float a = sc[h * 132 + m];
        F2U ad; ad.f = make_float2(a, a);
        const float4* xr = (const float4*)(x + (long long)(s0 + m) * D_DRUG + j0);
#pragma unroll
        for (int r = 0; r < 4; r++) {
            float4 v = xr[r];
            F2U b0, b1;
            b0.f = make_float2(v.x, v.y);
            b1.f = make_float2(v.z, v.w);
            fma2(acc[2 * r], ad, b0);
            fma2(acc[2 * r + 1], ad, b1);
        }
    }
    long long base = (long long)b * (NHEAD * D_DRUG) + h * D_DRUG + j0;
#pragma unroll
    for (int i = 0; i < 8; i++) {
        float va = acc[i].f.x, vb = acc[i].f.y;
        __nv_bfloat16 ha = __float2bfloat16(va), hb = __float2bfloat16(vb);
        uint32_t ph = (uint32_t)__bfloat16_as_ushort(ha)
                    | ((uint32_t)__bfloat16_as_ushort(hb) << 16);
        uint32_t pl = pack_bf16(va - __bfloat162float(ha), vb - __bfloat162float(hb));
        *(uint32_t*)(xah + base + i * 2) = ph;
        *(uint32_t*)(xal + base + i * 2) = pl;
    }
}

// ---------------------------------------------------------------------------
// Launch
// ---------------------------------------------------------------------------
extern "C" void kernel_launch(void* const* d_in, const int* in_sizes, int n_in,
                              void* d_out, int out_size)
{
    const float* x_nodes = (const float*)d_in[0];
    const float* cell    = (const float*)d_in[1];
    const float* Wq      = (const float*)d_in[2];
    const float* bq      = (const float*)d_in[3];
    const float* Wk      = (const float*)d_in[4];
    /* bk cancels in softmax */
    const float* Wv      = (const float*)d_in[6];
    const float* bv      = (const float*)d_in[7];
    const float* Wo      = (const float*)d_in[8];
    const float* bo      = (const float*)d_in[9];
    const float* Wc      = (const float*)d_in[10];
    const float* bc      = (const float*)d_in[11];
    const void*  guide   = d_in[12];
    float*       out     = (float*)d_out;

    int N = in_sizes[12];

    float *qkp, *part; int* seg;
    __nv_bfloat16 *a0h, *a0l, *a1h, *a1l, *xah, *xal;
    __nv_bfloat16 *wch, *wcl, *wqh, *wql, *woh, *wol, *wvh, *wvl, *wkth, *wktl;
    cudaGetSymbolAddress((void**)&qkp,  g_qk);
    cudaGetSymbolAddress((void**)&part, g_part);
    cudaGetSymbolAddress((void**)&seg,  g_seg);
    cudaGetSymbolAddress((void**)&a0h,  g_a0h);
    cudaGetSymbolAddress((void**)&a0l,  g_a0l);
    cudaGetSymbolAddress((void**)&a1h,  g_a1h);
    cudaGetSymbolAddress((void**)&a1l,  g_a1l);
    cudaGetSymbolAddress((void**)&xah,  g_xah);
    cudaGetSymbolAddress((void**)&xal,  g_xal);
    cudaGetSymbolAddress((void**)&wch,  g_wch);
    cudaGetSymbolAddress((void**)&wcl,  g_wcl);
    cudaGetSymbolAddress((void**)&wqh,  g_wqh);
    cudaGetSymbolAddress((void**)&wql,  g_wql);
    cudaGetSymbolAddress((void**)&woh,  g_woh);
    cudaGetSymbolAddress((void**)&wol,  g_wol);
    cudaGetSymbolAddress((void**)&wvh,  g_wvh);
    cudaGetSymbolAddress((void**)&wvl,  g_wvl);
    cudaGetSymbolAddress((void**)&wkth, g_wkth);
    cudaGetSymbolAddress((void**)&wktl, g_wktl);

    const long long PSTR = (long long)BATCH * EMB;

    // 1: fused prep (seg + copy + all splits)
    prep_kernel<<<4611, 256>>>((const float4*)Wc, (const float4*)Wq, (const float4*)Wo,
                               (const float4*)Wv, (const float4*)cell, Wk, guide, N,
                               (uint2*)wch, (uint2*)wcl, (uint2*)wqh, (uint2*)wql,
                               (uint2*)woh, (uint2*)wol, (uint2*)wvh, (uint2*)wvl,
                               (uint2*)a0h, (uint2*)a0l, wkth, wktl, seg, (float4*)out);

    // 2: G1 cq = cell @ Wc^T (split-K4)
    mma_gemm3x<2><<<dim3(16, 8, 4), 256>>>(
        a0h, a0l, D_CELL, 0, wch, wcl, D_CELL, 0, nullptr, 0,
        part, EMB, 0, 1.0f, 256, 4, PSTR);
    // 3: reduce +bc -> a1 hi/lo
    reduce_k<0><<<512, 256>>>((const float4*)part, bc, nullptr, a1h, a1l, EMB, 1.0f, 4);

    // 4 (profiled slot): G2 q = cq @ Wq^T (split-K4)
    mma_gemm3x<2><<<dim3(16, 8, 4), 256>>>(
        a1h, a1l, EMB, 0, wqh, wql, EMB, 0, nullptr, 0,
        part, EMB, 0, 1.0f, 256, 4, PSTR);
    // 5: reduce (+bq)*0.125 -> a0 hi/lo
    reduce_k<0><<<512, 256>>>((const float4*)part, bq, nullptr, a0h, a0l, EMB, 0.125f, 4);

    // 6: qk = q @ WkT per head
    mma_gemm3x<1><<<dim3(4, 8, 16), 256>>>(
        a0h, a0l, EMB, HDIM, wkth, wktl, HDIM, (long long)D_DRUG * HDIM, nullptr, 0,
        qkp, NHEAD * D_DRUG, D_DRUG, 1.0f, HDIM, 1, 0);

    // 7: attention
    attn_kernel<<<512, 256>>>(x_nodes, qkp, seg, xah, xal);

    // 8: vv per head (split-K2)
    mma_gemm3x<2><<<dim3(1, 8, 32), 256>>>(
        xah, xal, NHEAD * D_DRUG, D_DRUG, wvh, wvl, D_DRUG, (long long)HDIM * D_DRUG,
        nullptr, 0, part, EMB, HDIM, 1.0f, 128, 2, PSTR);
    // 9: reduce +bv -> a1 hi/lo
    reduce_k<0><<<512, 256>>>((const float4*)part, bv, nullptr, a1h, a1l, EMB, 1.0f, 2);

    // 10: G3 out = op @ Wo^T (split-K4)
    mma_gemm3x<2><<<dim3(16, 8, 4), 256>>>(
        a1h, a1l, EMB, 0, woh, wol, EMB, 0, nullptr, 0,
        part, EMB, 0, 1.0f, 256, 4, PSTR);
    // 11: reduce +bo -> fp32 strided into out
    reduce_k<1><<<512, 256>>>((const float4*)part, bo, out, nullptr, nullptr,
                              EMB + D_CELL, 1.0f, 4);

    (void)n_in; (void)out_size;
}